// round 1
// baseline (speedup 1.0000x reference)
#include <cuda_runtime.h>
#include <math.h>
#include <stdint.h>

#define N_NODES 100000
#define N_EDGES 1600000
#define KIN 128
#define HGAT 4
#define D1 32
#define HD1 128
#define D2 47
#define HD2 188

// ---------------- scratch (static device globals; no allocation) ----------------
__device__ int   g_counts[N_NODES + 1];
__device__ int   g_rowoff[N_NODES + 1];
__device__ int   g_bsums[128];
__device__ int   g_csr_src[N_EDGES];
__device__ int   g_slot[N_EDGES];
__device__ float g_feat1[(size_t)N_NODES * HD1];
__device__ float g_out1 [(size_t)N_NODES * HD1];
__device__ float g_feat2[(size_t)N_NODES * HD2];
__device__ float g_el[N_NODES * 4];
__device__ float g_er[N_NODES * 4];
__device__ float g_m [N_NODES * 4];
__device__ float g_is[N_NODES * 4];
__device__ float g_alpha[(size_t)N_EDGES * 4];

// ---------------- small utility kernels ----------------
__global__ void zero_counts_k(int n) {
    int i = blockIdx.x * blockDim.x + threadIdx.x;
    if (i < n) g_counts[i] = 0;
}

__global__ void hist_k(const int* __restrict__ dst) {
    int e = blockIdx.x * blockDim.x + threadIdx.x;
    if (e < N_EDGES) atomicAdd(&g_counts[dst[e]], 1);
}

__global__ void scan_block_k(int n) {
    __shared__ int sh[1024];
    int i = blockIdx.x * 1024 + threadIdx.x;
    int v = (i < n) ? g_counts[i] : 0;
    sh[threadIdx.x] = v;
    __syncthreads();
    for (int off = 1; off < 1024; off <<= 1) {
        int t = (threadIdx.x >= off) ? sh[threadIdx.x - off] : 0;
        __syncthreads();
        sh[threadIdx.x] += t;
        __syncthreads();
    }
    if (i < n) g_rowoff[i] = sh[threadIdx.x] - v;  // exclusive
    if (threadIdx.x == 1023) g_bsums[blockIdx.x] = sh[1023];
}

__global__ void scan_sums_k(int nb) {
    if (threadIdx.x == 0 && blockIdx.x == 0) {
        int run = 0;
        for (int i = 0; i < nb; i++) { int v = g_bsums[i]; g_bsums[i] = run; run += v; }
    }
}

__global__ void scan_add_k(int n) {
    int i = blockIdx.x * 1024 + threadIdx.x;
    if (i < n) g_rowoff[i] += g_bsums[blockIdx.x];
}

__global__ void scatter_k(const int* __restrict__ src, const int* __restrict__ dst) {
    int e = blockIdx.x * blockDim.x + threadIdx.x;
    if (e >= N_EDGES) return;
    int d = dst[e];
    int pos = atomicAdd(&g_counts[d], 1);
    int slot = g_rowoff[d] + pos;
    g_csr_src[slot] = src[e];
    g_slot[e] = slot;
}

// ---------------- GEMM: C[nrows x kout] = A[nrows x 128] @ W[128 x kout] ----------------
// BM=64, BN=64, full K=128 resident in smem. Optional row indirection on A.
template <bool IND>
__global__ void __launch_bounds__(256) gemm_k(
    const float* __restrict__ A, const float* __restrict__ W,
    float* __restrict__ C, const int* __restrict__ ridx,
    int nrows, int kout)
{
    extern __shared__ float smem[];
    float* As = smem;              // [128][65] transposed (padded)
    float* Bs = smem + 128 * 65;   // [128][64]

    int t = threadIdx.x;
    int rowb = blockIdx.x * 64;
    int colb = blockIdx.y * 64;

    // Load A tile, transposed into As[k][r]
    #pragma unroll
    for (int i = 0; i < 8; i++) {
        int flat = t + i * 256;            // float4 units, 0..2047
        int rl = flat >> 5;                // 0..63
        int k4 = (flat & 31) << 2;         // 0..124
        int rg = rowb + rl;
        float4 v = make_float4(0.f, 0.f, 0.f, 0.f);
        if (rg < nrows) {
            int ra = IND ? ridx[rg] : rg;
            v = *reinterpret_cast<const float4*>(A + (size_t)ra * KIN + k4);
        }
        As[(k4 + 0) * 65 + rl] = v.x;
        As[(k4 + 1) * 65 + rl] = v.y;
        As[(k4 + 2) * 65 + rl] = v.z;
        As[(k4 + 3) * 65 + rl] = v.w;
    }
    // Load B tile Bs[k][c]
    #pragma unroll
    for (int i = 0; i < 8; i++) {
        int flat = t + i * 256;
        int k  = flat >> 4;                // 0..127
        int c4 = (flat & 15) << 2;         // 0..60
        int cg = colb + c4;
        float4 v = make_float4(0.f, 0.f, 0.f, 0.f);
        if (cg + 3 < kout)
            v = *reinterpret_cast<const float4*>(W + (size_t)k * kout + cg);
        *reinterpret_cast<float4*>(Bs + k * 64 + c4) = v;
    }
    __syncthreads();

    int tr4 = (t >> 4) << 2;
    int tc4 = (t & 15) << 2;
    float acc[4][4];
    #pragma unroll
    for (int i = 0; i < 4; i++)
        #pragma unroll
        for (int j = 0; j < 4; j++) acc[i][j] = 0.f;

    #pragma unroll 8
    for (int k = 0; k < 128; k++) {
        float a0 = As[k * 65 + tr4 + 0];
        float a1 = As[k * 65 + tr4 + 1];
        float a2 = As[k * 65 + tr4 + 2];
        float a3 = As[k * 65 + tr4 + 3];
        float4 b = *reinterpret_cast<const float4*>(Bs + k * 64 + tc4);
        acc[0][0] = fmaf(a0, b.x, acc[0][0]); acc[0][1] = fmaf(a0, b.y, acc[0][1]);
        acc[0][2] = fmaf(a0, b.z, acc[0][2]); acc[0][3] = fmaf(a0, b.w, acc[0][3]);
        acc[1][0] = fmaf(a1, b.x, acc[1][0]); acc[1][1] = fmaf(a1, b.y, acc[1][1]);
        acc[1][2] = fmaf(a1, b.z, acc[1][2]); acc[1][3] = fmaf(a1, b.w, acc[1][3]);
        acc[2][0] = fmaf(a2, b.x, acc[2][0]); acc[2][1] = fmaf(a2, b.y, acc[2][1]);
        acc[2][2] = fmaf(a2, b.z, acc[2][2]); acc[2][3] = fmaf(a2, b.w, acc[2][3]);
        acc[3][0] = fmaf(a3, b.x, acc[3][0]); acc[3][1] = fmaf(a3, b.y, acc[3][1]);
        acc[3][2] = fmaf(a3, b.z, acc[3][2]); acc[3][3] = fmaf(a3, b.w, acc[3][3]);
    }

    #pragma unroll
    for (int i = 0; i < 4; i++) {
        int rg = rowb + tr4 + i;
        if (rg >= nrows) continue;
        int cg = colb + tc4;
        if (cg + 3 < kout) {
            float4 v = make_float4(acc[i][0], acc[i][1], acc[i][2], acc[i][3]);
            *reinterpret_cast<float4*>(C + (size_t)rg * kout + cg) = v;
        }
    }
}

// ---------------- el/er: per-node per-head attention dot products ----------------
__global__ void eler_k(const float* __restrict__ feat,
                       const float* __restrict__ al, const float* __restrict__ ar,
                       int hd, int d)
{
    int w = (blockIdx.x * blockDim.x + threadIdx.x) >> 5;
    int lane = threadIdx.x & 31;
    if (w >= N_NODES) return;
    float aL[4] = {0.f, 0.f, 0.f, 0.f};
    float aR[4] = {0.f, 0.f, 0.f, 0.f};
    const float* f = feat + (size_t)w * hd;
    for (int j = lane; j < hd; j += 32) {
        float v = f[j];
        int h = j / d;
        int dd = j - h * d;
        aL[h] = fmaf(v, al[h * d + dd], aL[h]);
        aR[h] = fmaf(v, ar[h * d + dd], aR[h]);
    }
    #pragma unroll
    for (int h = 0; h < 4; h++) {
        #pragma unroll
        for (int off = 16; off; off >>= 1) {
            aL[h] += __shfl_xor_sync(0xffffffffu, aL[h], off);
            aR[h] += __shfl_xor_sync(0xffffffffu, aR[h], off);
        }
    }
    if (lane == 0) {
        *reinterpret_cast<float4*>(g_el + (size_t)w * 4) = make_float4(aL[0], aL[1], aL[2], aL[3]);
        *reinterpret_cast<float4*>(g_er + (size_t)w * 4) = make_float4(aR[0], aR[1], aR[2], aR[3]);
    }
}

// ---------------- per-node online softmax stats (max, 1/sum) over CSR edges ----------------
__global__ void attn_ms_k()
{
    int w = (blockIdx.x * blockDim.x + threadIdx.x) >> 5;
    int lane = threadIdx.x & 31;
    if (w >= N_NODES) return;
    int s0 = g_rowoff[w], e0 = g_rowoff[w + 1];
    float4 erd = *reinterpret_cast<const float4*>(g_er + (size_t)w * 4);
    float mx[4] = {-1e30f, -1e30f, -1e30f, -1e30f};
    float sm[4] = {0.f, 0.f, 0.f, 0.f};
    for (int i = s0 + lane; i < e0; i += 32) {
        int sn = g_csr_src[i];
        float4 eL = *reinterpret_cast<const float4*>(g_el + (size_t)sn * 4);
        float ev[4] = {eL.x + erd.x, eL.y + erd.y, eL.z + erd.z, eL.w + erd.w};
        #pragma unroll
        for (int h = 0; h < 4; h++) {
            float e = ev[h];
            e = fmaxf(e, 0.2f * e);               // LeakyReLU
            float nm = fmaxf(mx[h], e);
            sm[h] = sm[h] * __expf(mx[h] - nm) + __expf(e - nm);
            mx[h] = nm;
        }
    }
    #pragma unroll
    for (int off = 16; off; off >>= 1) {
        #pragma unroll
        for (int h = 0; h < 4; h++) {
            float om = __shfl_xor_sync(0xffffffffu, mx[h], off);
            float os = __shfl_xor_sync(0xffffffffu, sm[h], off);
            float nm = fmaxf(mx[h], om);
            sm[h] = sm[h] * __expf(mx[h] - nm) + os * __expf(om - nm);
            mx[h] = nm;
        }
    }
    if (lane == 0) {
        *reinterpret_cast<float4*>(g_m + (size_t)w * 4) = make_float4(mx[0], mx[1], mx[2], mx[3]);
        float4 inv;
        inv.x = 1.0f / fmaxf(sm[0], 1e-9f);
        inv.y = 1.0f / fmaxf(sm[1], 1e-9f);
        inv.z = 1.0f / fmaxf(sm[2], 1e-9f);
        inv.w = 1.0f / fmaxf(sm[3], 1e-9f);
        *reinterpret_cast<float4*>(g_is + (size_t)w * 4) = inv;
    }
}

// ---------------- per-edge alpha, written pre-permuted into CSR slot order ----------------
__global__ void alpha_k(const int* __restrict__ src, const int* __restrict__ dst)
{
    int e = blockIdx.x * blockDim.x + threadIdx.x;
    if (e >= N_EDGES) return;
    int sn = src[e], dn = dst[e];
    float4 eL = *reinterpret_cast<const float4*>(g_el + (size_t)sn * 4);
    float4 eR = *reinterpret_cast<const float4*>(g_er + (size_t)dn * 4);
    float4 mm = *reinterpret_cast<const float4*>(g_m  + (size_t)dn * 4);
    float4 ss = *reinterpret_cast<const float4*>(g_is + (size_t)dn * 4);
    float4 a;
    float v;
    v = eL.x + eR.x; v = fmaxf(v, 0.2f * v); a.x = __expf(v - mm.x) * ss.x;
    v = eL.y + eR.y; v = fmaxf(v, 0.2f * v); a.y = __expf(v - mm.y) * ss.y;
    v = eL.z + eR.z; v = fmaxf(v, 0.2f * v); a.z = __expf(v - mm.z) * ss.z;
    v = eL.w + eR.w; v = fmaxf(v, 0.2f * v); a.w = __expf(v - mm.w) * ss.w;
    *reinterpret_cast<float4*>(g_alpha + (size_t)g_slot[e] * 4) = a;
}

// ---------------- layer-1 aggregation: warp per node, 128 dims, ELU + bias ----------------
__global__ void agg1_k(const float* __restrict__ b1)
{
    int w = (blockIdx.x * blockDim.x + threadIdx.x) >> 5;
    int lane = threadIdx.x & 31;
    if (w >= N_NODES) return;
    int s0 = g_rowoff[w], e0 = g_rowoff[w + 1];
    int hd = lane >> 3;  // head owning dims lane*4..lane*4+3
    const float4* fv = reinterpret_cast<const float4*>(g_feat1);
    float4 acc = make_float4(0.f, 0.f, 0.f, 0.f);
    int i = s0;
    for (; i + 1 < e0; i += 2) {
        int s1 = g_csr_src[i];
        int s2 = g_csr_src[i + 1];
        float a1 = g_alpha[(size_t)i * 4 + hd];
        float a2 = g_alpha[(size_t)(i + 1) * 4 + hd];
        float4 f1 = fv[(size_t)s1 * 32 + lane];
        float4 f2 = fv[(size_t)s2 * 32 + lane];
        acc.x = fmaf(f1.x, a1, acc.x); acc.y = fmaf(f1.y, a1, acc.y);
        acc.z = fmaf(f1.z, a1, acc.z); acc.w = fmaf(f1.w, a1, acc.w);
        acc.x = fmaf(f2.x, a2, acc.x); acc.y = fmaf(f2.y, a2, acc.y);
        acc.z = fmaf(f2.z, a2, acc.z); acc.w = fmaf(f2.w, a2, acc.w);
    }
    if (i < e0) {
        int s1 = g_csr_src[i];
        float a1 = g_alpha[(size_t)i * 4 + hd];
        float4 f1 = fv[(size_t)s1 * 32 + lane];
        acc.x = fmaf(f1.x, a1, acc.x); acc.y = fmaf(f1.y, a1, acc.y);
        acc.z = fmaf(f1.z, a1, acc.z); acc.w = fmaf(f1.w, a1, acc.w);
    }
    float4 bb = *reinterpret_cast<const float4*>(b1 + lane * 4);
    acc.x += bb.x; acc.y += bb.y; acc.z += bb.z; acc.w += bb.w;
    acc.x = (acc.x > 0.f) ? acc.x : (__expf(acc.x) - 1.f);
    acc.y = (acc.y > 0.f) ? acc.y : (__expf(acc.y) - 1.f);
    acc.z = (acc.z > 0.f) ? acc.z : (__expf(acc.z) - 1.f);
    acc.w = (acc.w > 0.f) ? acc.w : (__expf(acc.w) - 1.f);
    *reinterpret_cast<float4*>(g_out1 + (size_t)w * HD1 + lane * 4) = acc;
}

// ---------------- layer-2 aggregation: warp per node, 188 dims, bias + head-mean ----------------
__global__ void agg2_k(const float* __restrict__ b2, float* __restrict__ out)
{
    __shared__ float sbuf[8][HD2];
    int wl = threadIdx.x >> 5;
    int w = blockIdx.x * 8 + wl;
    int lane = threadIdx.x & 31;
    if (w >= N_NODES) return;
    int s0 = g_rowoff[w], e0 = g_rowoff[w + 1];
    float acc[6] = {0.f, 0.f, 0.f, 0.f, 0.f, 0.f};
    int hh[6];
    #pragma unroll
    for (int k = 0; k < 6; k++) {
        int j = lane + 32 * k;
        hh[k] = (j < HD2) ? (j / 47) : 0;
    }
    for (int i = s0; i < e0; i++) {
        int sn = g_csr_src[i];
        float4 a4 = *reinterpret_cast<const float4*>(g_alpha + (size_t)i * 4);
        const float* f = g_feat2 + (size_t)sn * HD2;
        #pragma unroll
        for (int k = 0; k < 6; k++) {
            int j = lane + 32 * k;
            if (j < HD2) {
                float a = (hh[k] == 0) ? a4.x : (hh[k] == 1) ? a4.y : (hh[k] == 2) ? a4.z : a4.w;
                acc[k] = fmaf(f[j], a, acc[k]);
            }
        }
    }
    #pragma unroll
    for (int k = 0; k < 6; k++) {
        int j = lane + 32 * k;
        if (j < HD2) sbuf[wl][j] = acc[k] + b2[j];
    }
    __syncwarp();
    for (int c = lane; c < 47; c += 32) {
        float v = sbuf[wl][c] + sbuf[wl][47 + c] + sbuf[wl][94 + c] + sbuf[wl][141 + c];
        out[(size_t)w * 47 + c] = 0.25f * v;
    }
}

// ---------------- host launcher ----------------
extern "C" void kernel_launch(void* const* d_in, const int* in_sizes, int n_in,
                              void* d_out, int out_size)
{
    const float* x   = (const float*)d_in[0];
    const int*   src = (const int*)  d_in[1];
    const int*   dst = (const int*)  d_in[2];
    const int*   inv = (const int*)  d_in[3];
    const float* W1  = (const float*)d_in[4];
    const float* al1 = (const float*)d_in[5];
    const float* ar1 = (const float*)d_in[6];
    const float* b1  = (const float*)d_in[7];
    const float* W2  = (const float*)d_in[8];
    const float* al2 = (const float*)d_in[9];
    const float* ar2 = (const float*)d_in[10];
    const float* b2  = (const float*)d_in[11];
    float* out = (float*)d_out;
    (void)in_sizes; (void)n_in; (void)out_size;

    void *p_feat1 = nullptr, *p_out1 = nullptr, *p_feat2 = nullptr;
    cudaGetSymbolAddress(&p_feat1, g_feat1);
    cudaGetSymbolAddress(&p_out1,  g_out1);
    cudaGetSymbolAddress(&p_feat2, g_feat2);

    const int NP1 = N_NODES + 1;
    const int SCAN_BLOCKS = (NP1 + 1023) / 1024;
    const int EB = (N_EDGES + 255) / 256;
    const int NODE_WARP_BLOCKS = (N_NODES + 7) / 8;  // 8 warps/block

    // CSR build
    zero_counts_k<<<(NP1 + 255) / 256, 256>>>(NP1);
    hist_k<<<EB, 256>>>(dst);
    scan_block_k<<<SCAN_BLOCKS, 1024>>>(NP1);
    scan_sums_k<<<1, 32>>>(SCAN_BLOCKS);
    scan_add_k<<<SCAN_BLOCKS, 1024>>>(NP1);
    zero_counts_k<<<(NP1 + 255) / 256, 256>>>(NP1);
    scatter_k<<<EB, 256>>>(src, dst);

    size_t gsm = (size_t)(128 * 65 + 128 * 64) * sizeof(float);  // 66048 B
    cudaFuncSetAttribute(gemm_k<false>, cudaFuncAttributeMaxDynamicSharedMemorySize, (int)gsm);
    cudaFuncSetAttribute(gemm_k<true>,  cudaFuncAttributeMaxDynamicSharedMemorySize, (int)gsm);

    // ---- Layer 1 ----
    dim3 g1((N_NODES + 63) / 64, (HD1 + 63) / 64);
    gemm_k<false><<<g1, 256, gsm>>>(x, W1, (float*)p_feat1, nullptr, N_NODES, HD1);
    eler_k<<<NODE_WARP_BLOCKS, 256>>>((const float*)p_feat1, al1, ar1, HD1, D1);
    attn_ms_k<<<NODE_WARP_BLOCKS, 256>>>();
    alpha_k<<<EB, 256>>>(src, dst);
    agg1_k<<<NODE_WARP_BLOCKS, 256>>>(b1);

    // ---- Layer 2 (A rows gathered through inverse_idx inside the GEMM) ----
    dim3 g2((N_NODES + 63) / 64, (HD2 + 63) / 64);
    gemm_k<true><<<g2, 256, gsm>>>((const float*)p_out1, W2, (float*)p_feat2, inv, N_NODES, HD2);
    eler_k<<<NODE_WARP_BLOCKS, 256>>>((const float*)p_feat2, al2, ar2, HD2, D2);
    attn_ms_k<<<NODE_WARP_BLOCKS, 256>>>();
    alpha_k<<<EB, 256>>>(src, dst);
    agg2_k<<<NODE_WARP_BLOCKS, 256>>>(b2, out);
}

// round 2
// speedup vs baseline: 1.0931x; 1.0931x over previous
#include <cuda_runtime.h>
#include <math.h>
#include <stdint.h>

#define N_NODES 100000
#define N_EDGES 1600000
#define KIN 128
#define D1 32
#define HD1 128
#define D2 47
#define HD2 188

// ---------------- scratch (static device globals; no allocation) ----------------
__device__ int   g_counts[N_NODES + 1];
__device__ int   g_rowoff[N_NODES + 1];
__device__ int   g_bsums[128];
__device__ int   g_csr_src[N_EDGES];
__device__ float g_feat1[(size_t)N_NODES * HD1];
__device__ float g_out1 [(size_t)N_NODES * HD1];
__device__ float g_feat2[(size_t)N_NODES * HD2];
__device__ float g_el[N_NODES * 4];
__device__ float g_er[N_NODES * 4];
__device__ float g_alpha[(size_t)N_EDGES * 4];

// ---------------- packed f32x2 helpers (sm_103a FFMA2 path, PTX-only) ----------------
__device__ __forceinline__ void ffma2(unsigned long long& d, unsigned long long a, unsigned long long b) {
    asm("fma.rn.f32x2 %0, %1, %2, %0;" : "+l"(d) : "l"(a), "l"(b));
}
__device__ __forceinline__ unsigned long long splat2(float x) {
    unsigned long long r; unsigned int u = __float_as_uint(x);
    asm("mov.b64 %0, {%1, %1};" : "=l"(r) : "r"(u));
    return r;
}
__device__ __forceinline__ float2 unpack2(unsigned long long v) {
    unsigned int lo, hi;
    asm("mov.b64 {%0, %1}, %2;" : "=r"(lo), "=r"(hi) : "l"(v));
    return make_float2(__uint_as_float(lo), __uint_as_float(hi));
}

// ---------------- small utility kernels ----------------
__global__ void zero_counts_k(int n) {
    int i = blockIdx.x * blockDim.x + threadIdx.x;
    if (i < n) g_counts[i] = 0;
}

__global__ void hist_k(const int* __restrict__ dst) {
    int e = blockIdx.x * blockDim.x + threadIdx.x;
    if (e < N_EDGES) atomicAdd(&g_counts[dst[e]], 1);
}

__global__ void scan_block_k(int n) {
    __shared__ int sh[1024];
    int i = blockIdx.x * 1024 + threadIdx.x;
    int v = (i < n) ? g_counts[i] : 0;
    sh[threadIdx.x] = v;
    __syncthreads();
    for (int off = 1; off < 1024; off <<= 1) {
        int t = (threadIdx.x >= off) ? sh[threadIdx.x - off] : 0;
        __syncthreads();
        sh[threadIdx.x] += t;
        __syncthreads();
    }
    if (i < n) g_rowoff[i] = sh[threadIdx.x] - v;  // exclusive
    if (threadIdx.x == 1023) g_bsums[blockIdx.x] = sh[1023];
}

// parallel exclusive scan of up to 128 block sums
__global__ void scan_sums_k(int nb) {
    __shared__ int sh[128];
    int t = threadIdx.x;
    int v = (t < nb) ? g_bsums[t] : 0;
    sh[t] = v;
    __syncthreads();
    for (int off = 1; off < 128; off <<= 1) {
        int u = (t >= off) ? sh[t - off] : 0;
        __syncthreads();
        sh[t] += u;
        __syncthreads();
    }
    if (t < nb) g_bsums[t] = sh[t] - v;  // exclusive
}

__global__ void scan_add_k(int n) {
    int i = blockIdx.x * 1024 + threadIdx.x;
    if (i < n) g_rowoff[i] += g_bsums[blockIdx.x];
}

__global__ void scatter_k(const int* __restrict__ src, const int* __restrict__ dst) {
    int e = blockIdx.x * blockDim.x + threadIdx.x;
    if (e >= N_EDGES) return;
    int d = dst[e];
    int pos = atomicAdd(&g_counts[d], 1);
    g_csr_src[g_rowoff[d] + pos] = src[e];
}

// ---------------- GEMM: C[nrows x kout] = A[nrows x 128] @ W[128 x kout] ----------------
// BM=64, BN=64, full K=128 in smem, FFMA2 inner loop. Optional row indirection on A.
template <bool IND>
__global__ void __launch_bounds__(256) gemm_k(
    const float* __restrict__ A, const float* __restrict__ W,
    float* __restrict__ C, const int* __restrict__ ridx,
    int nrows, int kout)
{
    extern __shared__ float smem[];
    float* As = smem;              // [128][65] transposed (padded)
    float* Bs = smem + 128 * 65;   // [128][64]

    int t = threadIdx.x;
    int rowb = blockIdx.x * 64;
    int colb = blockIdx.y * 64;

    // Load A tile, transposed into As[k][r]
    #pragma unroll
    for (int i = 0; i < 8; i++) {
        int flat = t + i * 256;            // float4 units
        int rl = flat >> 5;                // 0..63
        int k4 = (flat & 31) << 2;         // 0..124
        int rg = rowb + rl;
        float4 v = make_float4(0.f, 0.f, 0.f, 0.f);
        if (rg < nrows) {
            int ra = IND ? ridx[rg] : rg;
            v = *reinterpret_cast<const float4*>(A + (size_t)ra * KIN + k4);
        }
        As[(k4 + 0) * 65 + rl] = v.x;
        As[(k4 + 1) * 65 + rl] = v.y;
        As[(k4 + 2) * 65 + rl] = v.z;
        As[(k4 + 3) * 65 + rl] = v.w;
    }
    // Load B tile Bs[k][c]
    #pragma unroll
    for (int i = 0; i < 8; i++) {
        int flat = t + i * 256;
        int k  = flat >> 4;                // 0..127
        int c4 = (flat & 15) << 2;         // 0..60
        int cg = colb + c4;
        float4 v = make_float4(0.f, 0.f, 0.f, 0.f);
        if (cg + 3 < kout)
            v = *reinterpret_cast<const float4*>(W + (size_t)k * kout + cg);
        *reinterpret_cast<float4*>(Bs + k * 64 + c4) = v;
    }
    __syncthreads();

    int tr4 = (t >> 4) << 2;
    int tc4 = (t & 15) << 2;
    unsigned long long acc2[4][2];
    #pragma unroll
    for (int i = 0; i < 4; i++) { acc2[i][0] = 0ull; acc2[i][1] = 0ull; }

    #pragma unroll 8
    for (int k = 0; k < 128; k++) {
        float a0 = As[k * 65 + tr4 + 0];
        float a1 = As[k * 65 + tr4 + 1];
        float a2 = As[k * 65 + tr4 + 2];
        float a3 = As[k * 65 + tr4 + 3];
        ulonglong2 b2 = *reinterpret_cast<const ulonglong2*>(Bs + k * 64 + tc4);
        unsigned long long s;
        s = splat2(a0); ffma2(acc2[0][0], s, b2.x); ffma2(acc2[0][1], s, b2.y);
        s = splat2(a1); ffma2(acc2[1][0], s, b2.x); ffma2(acc2[1][1], s, b2.y);
        s = splat2(a2); ffma2(acc2[2][0], s, b2.x); ffma2(acc2[2][1], s, b2.y);
        s = splat2(a3); ffma2(acc2[3][0], s, b2.x); ffma2(acc2[3][1], s, b2.y);
    }

    #pragma unroll
    for (int i = 0; i < 4; i++) {
        int rg = rowb + tr4 + i;
        if (rg >= nrows) continue;
        int cg = colb + tc4;
        if (cg + 3 < kout) {
            float2 p0 = unpack2(acc2[i][0]);
            float2 p1 = unpack2(acc2[i][1]);
            float4 v = make_float4(p0.x, p0.y, p1.x, p1.y);
            *reinterpret_cast<float4*>(C + (size_t)rg * kout + cg) = v;
        }
    }
}

// ---------------- el/er: per-node per-head attention dot products ----------------
__global__ void eler_k(const float* __restrict__ feat,
                       const float* __restrict__ al, const float* __restrict__ ar,
                       int hd, int d)
{
    int w = (blockIdx.x * blockDim.x + threadIdx.x) >> 5;
    int lane = threadIdx.x & 31;
    if (w >= N_NODES) return;
    float aL[4] = {0.f, 0.f, 0.f, 0.f};
    float aR[4] = {0.f, 0.f, 0.f, 0.f};
    const float* f = feat + (size_t)w * hd;
    for (int j = lane; j < hd; j += 32) {
        float v = f[j];
        int h = j / d;
        int dd = j - h * d;
        aL[h] = fmaf(v, al[h * d + dd], aL[h]);
        aR[h] = fmaf(v, ar[h * d + dd], aR[h]);
    }
    #pragma unroll
    for (int h = 0; h < 4; h++) {
        #pragma unroll
        for (int off = 16; off; off >>= 1) {
            aL[h] += __shfl_xor_sync(0xffffffffu, aL[h], off);
            aR[h] += __shfl_xor_sync(0xffffffffu, aR[h], off);
        }
    }
    if (lane == 0) {
        *reinterpret_cast<float4*>(g_el + (size_t)w * 4) = make_float4(aL[0], aL[1], aL[2], aL[3]);
        *reinterpret_cast<float4*>(g_er + (size_t)w * 4) = make_float4(aR[0], aR[1], aR[2], aR[3]);
    }
}

// ---------------- fused softmax stats + alpha (two passes over CSR edges) ----------------
__global__ void attn_alpha_k()
{
    int w = (blockIdx.x * blockDim.x + threadIdx.x) >> 5;
    int lane = threadIdx.x & 31;
    if (w >= N_NODES) return;
    int s0 = g_rowoff[w], e0 = g_rowoff[w + 1];
    if (s0 == e0) return;
    float4 erd = *reinterpret_cast<const float4*>(g_er + (size_t)w * 4);

    // pass 1: online max + sum per head
    float mx[4] = {-1e30f, -1e30f, -1e30f, -1e30f};
    float sm[4] = {0.f, 0.f, 0.f, 0.f};
    for (int i = s0 + lane; i < e0; i += 32) {
        int sn = g_csr_src[i];
        float4 eL = *reinterpret_cast<const float4*>(g_el + (size_t)sn * 4);
        float ev[4] = {eL.x + erd.x, eL.y + erd.y, eL.z + erd.z, eL.w + erd.w};
        #pragma unroll
        for (int h = 0; h < 4; h++) {
            float e = ev[h];
            e = fmaxf(e, 0.2f * e);               // LeakyReLU
            float nm = fmaxf(mx[h], e);
            sm[h] = sm[h] * __expf(mx[h] - nm) + __expf(e - nm);
            mx[h] = nm;
        }
    }
    #pragma unroll
    for (int off = 16; off; off >>= 1) {
        #pragma unroll
        for (int h = 0; h < 4; h++) {
            float om = __shfl_xor_sync(0xffffffffu, mx[h], off);
            float os = __shfl_xor_sync(0xffffffffu, sm[h], off);
            float nm = fmaxf(mx[h], om);
            sm[h] = sm[h] * __expf(mx[h] - nm) + os * __expf(om - nm);
            mx[h] = nm;
        }
    }
    float iv[4];
    #pragma unroll
    for (int h = 0; h < 4; h++) iv[h] = 1.0f / fmaxf(sm[h], 1e-9f);

    // pass 2: write alpha in CSR slot order (coalesced float4 stores)
    for (int i = s0 + lane; i < e0; i += 32) {
        int sn = g_csr_src[i];
        float4 eL = *reinterpret_cast<const float4*>(g_el + (size_t)sn * 4);
        float4 a;
        float v;
        v = eL.x + erd.x; v = fmaxf(v, 0.2f * v); a.x = __expf(v - mx[0]) * iv[0];
        v = eL.y + erd.y; v = fmaxf(v, 0.2f * v); a.y = __expf(v - mx[1]) * iv[1];
        v = eL.z + erd.z; v = fmaxf(v, 0.2f * v); a.z = __expf(v - mx[2]) * iv[2];
        v = eL.w + erd.w; v = fmaxf(v, 0.2f * v); a.w = __expf(v - mx[3]) * iv[3];
        *reinterpret_cast<float4*>(g_alpha + (size_t)i * 4) = a;
    }
}

// ---------------- layer-1 aggregation: warp per node, 128 dims, ELU + bias ----------------
__global__ void agg1_k(const float* __restrict__ b1)
{
    int w = (blockIdx.x * blockDim.x + threadIdx.x) >> 5;
    int lane = threadIdx.x & 31;
    if (w >= N_NODES) return;
    int s0 = g_rowoff[w], e0 = g_rowoff[w + 1];
    int hd = lane >> 3;  // head owning dims lane*4..lane*4+3
    const float4* fv = reinterpret_cast<const float4*>(g_feat1);
    float4 acc = make_float4(0.f, 0.f, 0.f, 0.f);
    int i = s0;
    for (; i + 1 < e0; i += 2) {
        int s1 = g_csr_src[i];
        int s2 = g_csr_src[i + 1];
        float a1 = g_alpha[(size_t)i * 4 + hd];
        float a2 = g_alpha[(size_t)(i + 1) * 4 + hd];
        float4 f1 = fv[(size_t)s1 * 32 + lane];
        float4 f2 = fv[(size_t)s2 * 32 + lane];
        acc.x = fmaf(f1.x, a1, acc.x); acc.y = fmaf(f1.y, a1, acc.y);
        acc.z = fmaf(f1.z, a1, acc.z); acc.w = fmaf(f1.w, a1, acc.w);
        acc.x = fmaf(f2.x, a2, acc.x); acc.y = fmaf(f2.y, a2, acc.y);
        acc.z = fmaf(f2.z, a2, acc.z); acc.w = fmaf(f2.w, a2, acc.w);
    }
    if (i < e0) {
        int s1 = g_csr_src[i];
        float a1 = g_alpha[(size_t)i * 4 + hd];
        float4 f1 = fv[(size_t)s1 * 32 + lane];
        acc.x = fmaf(f1.x, a1, acc.x); acc.y = fmaf(f1.y, a1, acc.y);
        acc.z = fmaf(f1.z, a1, acc.z); acc.w = fmaf(f1.w, a1, acc.w);
    }
    float4 bb = *reinterpret_cast<const float4*>(b1 + lane * 4);
    acc.x += bb.x; acc.y += bb.y; acc.z += bb.z; acc.w += bb.w;
    acc.x = (acc.x > 0.f) ? acc.x : (__expf(acc.x) - 1.f);
    acc.y = (acc.y > 0.f) ? acc.y : (__expf(acc.y) - 1.f);
    acc.z = (acc.z > 0.f) ? acc.z : (__expf(acc.z) - 1.f);
    acc.w = (acc.w > 0.f) ? acc.w : (__expf(acc.w) - 1.f);
    *reinterpret_cast<float4*>(g_out1 + (size_t)w * HD1 + lane * 4) = acc;
}

// ---------------- layer-2 aggregation: warp per node, 188 dims, bias + head-mean ----------------
__global__ void agg2_k(const float* __restrict__ b2, float* __restrict__ out)
{
    __shared__ float sbuf[8][HD2];
    int wl = threadIdx.x >> 5;
    int w = blockIdx.x * 8 + wl;
    int lane = threadIdx.x & 31;
    if (w >= N_NODES) return;
    int s0 = g_rowoff[w], e0 = g_rowoff[w + 1];
    float acc[6] = {0.f, 0.f, 0.f, 0.f, 0.f, 0.f};
    int hh[6];
    #pragma unroll
    for (int k = 0; k < 6; k++) {
        int j = lane + 32 * k;
        hh[k] = (j < HD2) ? (j / 47) : 0;
    }
    for (int i = s0; i < e0; i++) {
        int sn = g_csr_src[i];
        float4 a4 = *reinterpret_cast<const float4*>(g_alpha + (size_t)i * 4);
        const float* f = g_feat2 + (size_t)sn * HD2;
        #pragma unroll
        for (int k = 0; k < 6; k++) {
            int j = lane + 32 * k;
            if (j < HD2) {
                float a = (hh[k] == 0) ? a4.x : (hh[k] == 1) ? a4.y : (hh[k] == 2) ? a4.z : a4.w;
                acc[k] = fmaf(f[j], a, acc[k]);
            }
        }
    }
    #pragma unroll
    for (int k = 0; k < 6; k++) {
        int j = lane + 32 * k;
        if (j < HD2) sbuf[wl][j] = acc[k] + b2[j];
    }
    __syncwarp();
    for (int c = lane; c < 47; c += 32) {
        float v = sbuf[wl][c] + sbuf[wl][47 + c] + sbuf[wl][94 + c] + sbuf[wl][141 + c];
        out[(size_t)w * 47 + c] = 0.25f * v;
    }
}

// ---------------- host launcher ----------------
extern "C" void kernel_launch(void* const* d_in, const int* in_sizes, int n_in,
                              void* d_out, int out_size)
{
    const float* x   = (const float*)d_in[0];
    const int*   src = (const int*)  d_in[1];
    const int*   dst = (const int*)  d_in[2];
    const int*   inv = (const int*)  d_in[3];
    const float* W1  = (const float*)d_in[4];
    const float* al1 = (const float*)d_in[5];
    const float* ar1 = (const float*)d_in[6];
    const float* b1  = (const float*)d_in[7];
    const float* W2  = (const float*)d_in[8];
    const float* al2 = (const float*)d_in[9];
    const float* ar2 = (const float*)d_in[10];
    const float* b2  = (const float*)d_in[11];
    float* out = (float*)d_out;
    (void)in_sizes; (void)n_in; (void)out_size;

    void *p_feat1 = nullptr, *p_out1 = nullptr, *p_feat2 = nullptr;
    cudaGetSymbolAddress(&p_feat1, g_feat1);
    cudaGetSymbolAddress(&p_out1,  g_out1);
    cudaGetSymbolAddress(&p_feat2, g_feat2);

    const int NP1 = N_NODES + 1;
    const int SCAN_BLOCKS = (NP1 + 1023) / 1024;
    const int EB = (N_EDGES + 255) / 256;
    const int NODE_WARP_BLOCKS = (N_NODES + 7) / 8;  // 8 warps/block

    // CSR build
    zero_counts_k<<<(NP1 + 255) / 256, 256>>>(NP1);
    hist_k<<<EB, 256>>>(dst);
    scan_block_k<<<SCAN_BLOCKS, 1024>>>(NP1);
    scan_sums_k<<<1, 128>>>(SCAN_BLOCKS);
    scan_add_k<<<SCAN_BLOCKS, 1024>>>(NP1);
    zero_counts_k<<<(NP1 + 255) / 256, 256>>>(NP1);
    scatter_k<<<EB, 256>>>(src, dst);

    size_t gsm = (size_t)(128 * 65 + 128 * 64) * sizeof(float);  // 66048 B
    cudaFuncSetAttribute(gemm_k<false>, cudaFuncAttributeMaxDynamicSharedMemorySize, (int)gsm);
    cudaFuncSetAttribute(gemm_k<true>,  cudaFuncAttributeMaxDynamicSharedMemorySize, (int)gsm);

    // ---- Layer 1 ----
    dim3 g1((N_NODES + 63) / 64, (HD1 + 63) / 64);
    gemm_k<false><<<g1, 256, gsm>>>(x, W1, (float*)p_feat1, nullptr, N_NODES, HD1);
    eler_k<<<NODE_WARP_BLOCKS, 256>>>((const float*)p_feat1, al1, ar1, HD1, D1);
    attn_alpha_k<<<NODE_WARP_BLOCKS, 256>>>();
    agg1_k<<<NODE_WARP_BLOCKS, 256>>>(b1);

    // ---- Layer 2 (A rows gathered through inverse_idx inside the GEMM) ----
    dim3 g2((N_NODES + 63) / 64, (HD2 + 63) / 64);
    gemm_k<true><<<g2, 256, gsm>>>((const float*)p_out1, W2, (float*)p_feat2, inv, N_NODES, HD2);
    eler_k<<<NODE_WARP_BLOCKS, 256>>>((const float*)p_feat2, al2, ar2, HD2, D2);
    attn_alpha_k<<<NODE_WARP_BLOCKS, 256>>>();
    agg2_k<<<NODE_WARP_BLOCKS, 256>>>(b2, out);
}

// round 3
// speedup vs baseline: 1.2987x; 1.1880x over previous
#include <cuda_runtime.h>
#include <cuda_fp16.h>
#include <math.h>
#include <stdint.h>

#define N_NODES 100000
#define N_EDGES 1600000
#define KIN 128
#define HD1 128
#define HD2P 192   // padded 4*48 (real 4*47=188)

// ---------------- scratch (static device globals; no allocation) ----------------
__device__ int    g_counts[N_NODES + 1];
__device__ int    g_rowoff[N_NODES + 1];
__device__ int    g_bsums[128];
__device__ int    g_csr_src[N_EDGES];
__device__ __half g_feat1h[(size_t)N_NODES * HD1];
__device__ float  g_out1 [(size_t)N_NODES * HD1];
__device__ __half g_feat2h[(size_t)N_NODES * HD2P];
__device__ float  g_el[N_NODES * 4];
__device__ float  g_er[N_NODES * 4];
__device__ float  g_alpha[(size_t)N_EDGES * 4];
__device__ float  g_W2p[KIN * HD2P];
__device__ float  g_b2p[HD2P];
__device__ float  g_al2p[HD2P];
__device__ float  g_ar2p[HD2P];

// ---------------- packed f32x2 helpers (sm_103a FFMA2 path, PTX-only) ----------------
__device__ __forceinline__ void ffma2(unsigned long long& d, unsigned long long a, unsigned long long b) {
    asm("fma.rn.f32x2 %0, %1, %2, %0;" : "+l"(d) : "l"(a), "l"(b));
}
__device__ __forceinline__ unsigned long long splat2(float x) {
    unsigned long long r; unsigned int u = __float_as_uint(x);
    asm("mov.b64 %0, {%1, %1};" : "=l"(r) : "r"(u));
    return r;
}
__device__ __forceinline__ float2 unpack2(unsigned long long v) {
    unsigned int lo, hi;
    asm("mov.b64 {%0, %1}, %2;" : "=r"(lo), "=r"(hi) : "l"(v));
    return make_float2(__uint_as_float(lo), __uint_as_float(hi));
}

// ---------------- CSR build ----------------
__global__ void zero_counts_k(int n) {
    int i = blockIdx.x * blockDim.x + threadIdx.x;
    if (i < n) g_counts[i] = 0;
}
__global__ void hist_k(const int* __restrict__ dst) {
    int e = blockIdx.x * blockDim.x + threadIdx.x;
    if (e < N_EDGES) atomicAdd(&g_counts[dst[e]], 1);
}
__global__ void scan_block_k(int n) {
    __shared__ int sh[1024];
    int i = blockIdx.x * 1024 + threadIdx.x;
    int v = (i < n) ? g_counts[i] : 0;
    sh[threadIdx.x] = v;
    __syncthreads();
    for (int off = 1; off < 1024; off <<= 1) {
        int t = (threadIdx.x >= off) ? sh[threadIdx.x - off] : 0;
        __syncthreads();
        sh[threadIdx.x] += t;
        __syncthreads();
    }
    if (i < n) g_rowoff[i] = sh[threadIdx.x] - v;  // exclusive
    if (threadIdx.x == 1023) g_bsums[blockIdx.x] = sh[1023];
}
__global__ void scan_sums_k(int nb) {
    __shared__ int sh[128];
    int t = threadIdx.x;
    int v = (t < nb) ? g_bsums[t] : 0;
    sh[t] = v;
    __syncthreads();
    for (int off = 1; off < 128; off <<= 1) {
        int u = (t >= off) ? sh[t - off] : 0;
        __syncthreads();
        sh[t] += u;
        __syncthreads();
    }
    if (t < nb) g_bsums[t] = sh[t] - v;  // exclusive
}
__global__ void scan_add_k(int n) {
    int i = blockIdx.x * 1024 + threadIdx.x;
    if (i < n) g_rowoff[i] += g_bsums[blockIdx.x];
}
__global__ void scatter_k(const int* __restrict__ src, const int* __restrict__ dst) {
    int e = blockIdx.x * blockDim.x + threadIdx.x;
    if (e >= N_EDGES) return;
    int d = dst[e];
    int pos = atomicAdd(&g_counts[d], 1);
    g_csr_src[g_rowoff[d] + pos] = src[e];
}

// ---------------- pad layer-2 params into 4x48 layout ----------------
__global__ void pad2_k(const float* __restrict__ W2, const float* __restrict__ b2,
                       const float* __restrict__ al2, const float* __restrict__ ar2) {
    int i = blockIdx.x * blockDim.x + threadIdx.x;
    if (i < KIN * HD2P) {
        int k = i / HD2P, c = i % HD2P;
        int h = c / 48, dd = c % 48;
        g_W2p[i] = (dd < 47) ? W2[k * 188 + h * 47 + dd] : 0.0f;
    }
    if (i < HD2P) {
        int h = i / 48, dd = i % 48;
        float bv = (dd < 47) ? b2[h * 47 + dd] : 0.0f;
        float lv = (dd < 47) ? al2[h * 47 + dd] : 0.0f;
        float rv = (dd < 47) ? ar2[h * 47 + dd] : 0.0f;
        g_b2p[i] = bv; g_al2p[i] = lv; g_ar2p[i] = rv;
    }
}

// ---------------- GEMM: C[nrows x kout](half) = A[nrows x 128](f32) @ W[128 x kout] ----------------
// BM=128, BN=64, TPB=256, per-thread 8x4, FFMA2 inner loop. K=128 resident.
#define AS_S 132
template <bool IND>
__global__ void __launch_bounds__(256) gemm_k(
    const float* __restrict__ A, const float* __restrict__ W,
    __half* __restrict__ C, const int* __restrict__ ridx,
    int nrows, int kout)
{
    extern __shared__ float smem[];
    float* As = smem;                 // [128][AS_S] transposed As[k][r]
    float* Bs = smem + 128 * AS_S;    // [128][64]

    int t = threadIdx.x;
    int rowb = blockIdx.x * 128;
    int colb = blockIdx.y * 64;

    // Load A tile (coalesced rows), store transposed
    #pragma unroll
    for (int i = 0; i < 16; i++) {
        int flat = t + i * 256;            // float4 units, 0..4095
        int rl = flat >> 5;                // 0..127
        int k4 = (flat & 31) << 2;         // 0..124
        int rg = rowb + rl;
        float4 v = make_float4(0.f, 0.f, 0.f, 0.f);
        if (rg < nrows) {
            int ra = IND ? ridx[rg] : rg;
            v = *reinterpret_cast<const float4*>(A + (size_t)ra * KIN + k4);
        }
        As[(k4 + 0) * AS_S + rl] = v.x;
        As[(k4 + 1) * AS_S + rl] = v.y;
        As[(k4 + 2) * AS_S + rl] = v.z;
        As[(k4 + 3) * AS_S + rl] = v.w;
    }
    // Load B tile Bs[k][c]
    #pragma unroll
    for (int i = 0; i < 8; i++) {
        int flat = t + i * 256;
        int k  = flat >> 4;                // 0..127
        int c4 = (flat & 15) << 2;         // 0..60
        float4 v = *reinterpret_cast<const float4*>(W + (size_t)k * kout + colb + c4);
        *reinterpret_cast<float4*>(Bs + k * 64 + c4) = v;
    }
    __syncthreads();

    int rbase = (t >> 4) << 3;   // 8 rows
    int cbase = (t & 15) << 2;   // 4 cols
    unsigned long long acc2[8][2];
    #pragma unroll
    for (int i = 0; i < 8; i++) { acc2[i][0] = 0ull; acc2[i][1] = 0ull; }

    #pragma unroll 4
    for (int k = 0; k < 128; k++) {
        float4 a0 = *reinterpret_cast<const float4*>(As + k * AS_S + rbase);
        float4 a1 = *reinterpret_cast<const float4*>(As + k * AS_S + rbase + 4);
        ulonglong2 b2v = *reinterpret_cast<const ulonglong2*>(Bs + k * 64 + cbase);
        unsigned long long s;
        s = splat2(a0.x); ffma2(acc2[0][0], s, b2v.x); ffma2(acc2[0][1], s, b2v.y);
        s = splat2(a0.y); ffma2(acc2[1][0], s, b2v.x); ffma2(acc2[1][1], s, b2v.y);
        s = splat2(a0.z); ffma2(acc2[2][0], s, b2v.x); ffma2(acc2[2][1], s, b2v.y);
        s = splat2(a0.w); ffma2(acc2[3][0], s, b2v.x); ffma2(acc2[3][1], s, b2v.y);
        s = splat2(a1.x); ffma2(acc2[4][0], s, b2v.x); ffma2(acc2[4][1], s, b2v.y);
        s = splat2(a1.y); ffma2(acc2[5][0], s, b2v.x); ffma2(acc2[5][1], s, b2v.y);
        s = splat2(a1.z); ffma2(acc2[6][0], s, b2v.x); ffma2(acc2[6][1], s, b2v.y);
        s = splat2(a1.w); ffma2(acc2[7][0], s, b2v.x); ffma2(acc2[7][1], s, b2v.y);
    }

    #pragma unroll
    for (int i = 0; i < 8; i++) {
        int rg = rowb + rbase + i;
        if (rg >= nrows) continue;
        float2 p0 = unpack2(acc2[i][0]);
        float2 p1 = unpack2(acc2[i][1]);
        __half2 h0 = __float22half2_rn(p0);
        __half2 h1 = __float22half2_rn(p1);
        uint2 pk = make_uint2(*reinterpret_cast<unsigned int*>(&h0),
                              *reinterpret_cast<unsigned int*>(&h1));
        *reinterpret_cast<uint2*>(C + (size_t)rg * kout + colb + cbase) = pk;
    }
}

// ---------------- el/er: per-node per-head attention dots (half feats) ----------------
// Lane owns head lane>>3, dims [lane*dpl, lane*dpl+dpl). 8-lane segmented reduce.
__global__ void eler_k(const __half* __restrict__ feat,
                       const float* __restrict__ al, const float* __restrict__ ar,
                       int hd, int dpad, int dpl)
{
    int w = (blockIdx.x * blockDim.x + threadIdx.x) >> 5;
    int lane = threadIdx.x & 31;
    if (w >= N_NODES) return;
    int h = lane >> 3;
    const __half* f = feat + (size_t)w * hd + lane * dpl;
    const float* alh = al + h * dpad + (lane & 7) * dpl;
    const float* arh = ar + h * dpad + (lane & 7) * dpl;
    float accL = 0.f, accR = 0.f;
    for (int q = 0; q < dpl; q++) {
        float v = __half2float(f[q]);
        accL = fmaf(v, alh[q], accL);
        accR = fmaf(v, arh[q], accR);
    }
    #pragma unroll
    for (int off = 4; off; off >>= 1) {
        accL += __shfl_xor_sync(0xffffffffu, accL, off);
        accR += __shfl_xor_sync(0xffffffffu, accR, off);
    }
    float l0 = __shfl_sync(0xffffffffu, accL, 0);
    float l1 = __shfl_sync(0xffffffffu, accL, 8);
    float l2 = __shfl_sync(0xffffffffu, accL, 16);
    float l3 = __shfl_sync(0xffffffffu, accL, 24);
    float r0 = __shfl_sync(0xffffffffu, accR, 0);
    float r1 = __shfl_sync(0xffffffffu, accR, 8);
    float r2 = __shfl_sync(0xffffffffu, accR, 16);
    float r3 = __shfl_sync(0xffffffffu, accR, 24);
    if (lane == 0) {
        *reinterpret_cast<float4*>(g_el + (size_t)w * 4) = make_float4(l0, l1, l2, l3);
        *reinterpret_cast<float4*>(g_er + (size_t)w * 4) = make_float4(r0, r1, r2, r3);
    }
}

// ---------------- fused softmax stats + alpha (two passes over CSR edges) ----------------
__global__ void attn_alpha_k()
{
    int w = (blockIdx.x * blockDim.x + threadIdx.x) >> 5;
    int lane = threadIdx.x & 31;
    if (w >= N_NODES) return;
    int s0 = g_rowoff[w], e0 = g_rowoff[w + 1];
    if (s0 == e0) return;
    float4 erd = *reinterpret_cast<const float4*>(g_er + (size_t)w * 4);

    float mx[4] = {-1e30f, -1e30f, -1e30f, -1e30f};
    float sm[4] = {0.f, 0.f, 0.f, 0.f};
    for (int i = s0 + lane; i < e0; i += 32) {
        int sn = g_csr_src[i];
        float4 eL = *reinterpret_cast<const float4*>(g_el + (size_t)sn * 4);
        float ev[4] = {eL.x + erd.x, eL.y + erd.y, eL.z + erd.z, eL.w + erd.w};
        #pragma unroll
        for (int h = 0; h < 4; h++) {
            float e = ev[h];
            e = fmaxf(e, 0.2f * e);               // LeakyReLU
            float nm = fmaxf(mx[h], e);
            sm[h] = sm[h] * __expf(mx[h] - nm) + __expf(e - nm);
            mx[h] = nm;
        }
    }
    #pragma unroll
    for (int off = 16; off; off >>= 1) {
        #pragma unroll
        for (int h = 0; h < 4; h++) {
            float om = __shfl_xor_sync(0xffffffffu, mx[h], off);
            float os = __shfl_xor_sync(0xffffffffu, sm[h], off);
            float nm = fmaxf(mx[h], om);
            sm[h] = sm[h] * __expf(mx[h] - nm) + os * __expf(om - nm);
            mx[h] = nm;
        }
    }
    float iv[4];
    #pragma unroll
    for (int h = 0; h < 4; h++) iv[h] = 1.0f / fmaxf(sm[h], 1e-9f);

    for (int i = s0 + lane; i < e0; i += 32) {
        int sn = g_csr_src[i];
        float4 eL = *reinterpret_cast<const float4*>(g_el + (size_t)sn * 4);
        float4 a;
        float v;
        v = eL.x + erd.x; v = fmaxf(v, 0.2f * v); a.x = __expf(v - mx[0]) * iv[0];
        v = eL.y + erd.y; v = fmaxf(v, 0.2f * v); a.y = __expf(v - mx[1]) * iv[1];
        v = eL.z + erd.z; v = fmaxf(v, 0.2f * v); a.z = __expf(v - mx[2]) * iv[2];
        v = eL.w + erd.w; v = fmaxf(v, 0.2f * v); a.w = __expf(v - mx[3]) * iv[3];
        *reinterpret_cast<float4*>(g_alpha + (size_t)i * 4) = a;
    }
}

// ---------------- layer-1 aggregation: warp per node, half feats, ELU + bias ----------------
__global__ void agg1_k(const float* __restrict__ b1)
{
    int w = (blockIdx.x * blockDim.x + threadIdx.x) >> 5;
    int lane = threadIdx.x & 31;
    if (w >= N_NODES) return;
    int s0 = g_rowoff[w], e0 = g_rowoff[w + 1];
    int hd = lane >> 3;
    const uint2* fv = reinterpret_cast<const uint2*>(g_feat1h);  // 32 uint2 per row
    float4 acc = make_float4(0.f, 0.f, 0.f, 0.f);
    int i = s0;
    for (; i + 1 < e0; i += 2) {
        int s1 = g_csr_src[i];
        int s2 = g_csr_src[i + 1];
        float a1 = g_alpha[(size_t)i * 4 + hd];
        float a2 = g_alpha[(size_t)(i + 1) * 4 + hd];
        uint2 u1 = fv[(size_t)s1 * 32 + lane];
        uint2 u2 = fv[(size_t)s2 * 32 + lane];
        float2 f10 = __half22float2(*reinterpret_cast<__half2*>(&u1.x));
        float2 f11 = __half22float2(*reinterpret_cast<__half2*>(&u1.y));
        float2 f20 = __half22float2(*reinterpret_cast<__half2*>(&u2.x));
        float2 f21 = __half22float2(*reinterpret_cast<__half2*>(&u2.y));
        acc.x = fmaf(f10.x, a1, acc.x); acc.y = fmaf(f10.y, a1, acc.y);
        acc.z = fmaf(f11.x, a1, acc.z); acc.w = fmaf(f11.y, a1, acc.w);
        acc.x = fmaf(f20.x, a2, acc.x); acc.y = fmaf(f20.y, a2, acc.y);
        acc.z = fmaf(f21.x, a2, acc.z); acc.w = fmaf(f21.y, a2, acc.w);
    }
    if (i < e0) {
        int s1 = g_csr_src[i];
        float a1 = g_alpha[(size_t)i * 4 + hd];
        uint2 u1 = fv[(size_t)s1 * 32 + lane];
        float2 f10 = __half22float2(*reinterpret_cast<__half2*>(&u1.x));
        float2 f11 = __half22float2(*reinterpret_cast<__half2*>(&u1.y));
        acc.x = fmaf(f10.x, a1, acc.x); acc.y = fmaf(f10.y, a1, acc.y);
        acc.z = fmaf(f11.x, a1, acc.z); acc.w = fmaf(f11.y, a1, acc.w);
    }
    float4 bb = *reinterpret_cast<const float4*>(b1 + lane * 4);
    acc.x += bb.x; acc.y += bb.y; acc.z += bb.z; acc.w += bb.w;
    acc.x = (acc.x > 0.f) ? acc.x : (__expf(acc.x) - 1.f);
    acc.y = (acc.y > 0.f) ? acc.y : (__expf(acc.y) - 1.f);
    acc.z = (acc.z > 0.f) ? acc.z : (__expf(acc.z) - 1.f);
    acc.w = (acc.w > 0.f) ? acc.w : (__expf(acc.w) - 1.f);
    *reinterpret_cast<float4*>(g_out1 + (size_t)w * HD1 + lane * 4) = acc;
}

// ---------------- layer-2 aggregation: warp per node, padded half feats, bias + head-mean ----------------
__global__ void agg2_k(float* __restrict__ out)
{
    __shared__ float sbuf[8][HD2P];
    int wl = threadIdx.x >> 5;
    int w = blockIdx.x * 8 + wl;
    int lane = threadIdx.x & 31;
    if (w >= N_NODES) return;
    int s0 = g_rowoff[w], e0 = g_rowoff[w + 1];
    int h = lane >> 3;
    const unsigned int* fp = reinterpret_cast<const unsigned int*>(g_feat2h);  // 96 uints per row
    int lb = lane * 3;
    float acc[6] = {0.f, 0.f, 0.f, 0.f, 0.f, 0.f};
    for (int i = s0; i < e0; i++) {
        int sn = g_csr_src[i];
        float4 a4 = *reinterpret_cast<const float4*>(g_alpha + (size_t)i * 4);
        float a = (h < 2) ? (h == 0 ? a4.x : a4.y) : (h == 2 ? a4.z : a4.w);
        const unsigned int* f = fp + (size_t)sn * 96 + lb;
        unsigned int u0 = f[0], u1 = f[1], u2 = f[2];
        float2 p0 = __half22float2(*reinterpret_cast<__half2*>(&u0));
        float2 p1 = __half22float2(*reinterpret_cast<__half2*>(&u1));
        float2 p2 = __half22float2(*reinterpret_cast<__half2*>(&u2));
        acc[0] = fmaf(p0.x, a, acc[0]); acc[1] = fmaf(p0.y, a, acc[1]);
        acc[2] = fmaf(p1.x, a, acc[2]); acc[3] = fmaf(p1.y, a, acc[3]);
        acc[4] = fmaf(p2.x, a, acc[4]); acc[5] = fmaf(p2.y, a, acc[5]);
    }
    int db = lane * 6;
    #pragma unroll
    for (int q = 0; q < 6; q++)
        sbuf[wl][db + q] = acc[q] + g_b2p[db + q];
    __syncwarp();
    // head-mean over real 47 cols
    for (int c = lane; c < 47; c += 32) {
        float v = sbuf[wl][c] + sbuf[wl][48 + c] + sbuf[wl][96 + c] + sbuf[wl][144 + c];
        out[(size_t)w * 47 + c] = 0.25f * v;
    }
}

// ---------------- host launcher ----------------
extern "C" void kernel_launch(void* const* d_in, const int* in_sizes, int n_in,
                              void* d_out, int out_size)
{
    const float* x   = (const float*)d_in[0];
    const int*   src = (const int*)  d_in[1];
    const int*   dst = (const int*)  d_in[2];
    const int*   inv = (const int*)  d_in[3];
    const float* W1  = (const float*)d_in[4];
    const float* al1 = (const float*)d_in[5];
    const float* ar1 = (const float*)d_in[6];
    const float* b1  = (const float*)d_in[7];
    const float* W2  = (const float*)d_in[8];
    const float* al2 = (const float*)d_in[9];
    const float* ar2 = (const float*)d_in[10];
    const float* b2  = (const float*)d_in[11];
    float* out = (float*)d_out;
    (void)in_sizes; (void)n_in; (void)out_size;

    void *p_feat1 = nullptr, *p_out1 = nullptr, *p_feat2 = nullptr;
    void *p_W2p = nullptr, *p_al2p = nullptr, *p_ar2p = nullptr;
    cudaGetSymbolAddress(&p_feat1, g_feat1h);
    cudaGetSymbolAddress(&p_out1,  g_out1);
    cudaGetSymbolAddress(&p_feat2, g_feat2h);
    cudaGetSymbolAddress(&p_W2p,   g_W2p);
    cudaGetSymbolAddress(&p_al2p,  g_al2p);
    cudaGetSymbolAddress(&p_ar2p,  g_ar2p);

    const int NP1 = N_NODES + 1;
    const int SCAN_BLOCKS = (NP1 + 1023) / 1024;
    const int EB = (N_EDGES + 255) / 256;
    const int NODE_WARP_BLOCKS = (N_NODES + 7) / 8;  // 8 warps/block

    size_t gsm = (size_t)(128 * AS_S + 128 * 64) * sizeof(float);  // ~100KB
    cudaFuncSetAttribute(gemm_k<false>, cudaFuncAttributeMaxDynamicSharedMemorySize, (int)gsm);
    cudaFuncSetAttribute(gemm_k<true>,  cudaFuncAttributeMaxDynamicSharedMemorySize, (int)gsm);

    // launches 1-5: CSR scan prefix (gemm1 lands at slot 6 for the ncu -s 5 -c 1 window)
    zero_counts_k<<<(NP1 + 255) / 256, 256>>>(NP1);
    hist_k<<<EB, 256>>>(dst);
    scan_block_k<<<SCAN_BLOCKS, 1024>>>(NP1);
    scan_sums_k<<<1, 128>>>(SCAN_BLOCKS);
    scan_add_k<<<SCAN_BLOCKS, 1024>>>(NP1);

    // launch 6: GEMM1 (independent of CSR) — profiled by ncu
    dim3 g1((N_NODES + 127) / 128, HD1 / 64);
    gemm_k<false><<<g1, 256, gsm>>>(x, W1, (__half*)p_feat1, nullptr, N_NODES, HD1);

    // finish CSR
    zero_counts_k<<<(NP1 + 255) / 256, 256>>>(NP1);
    scatter_k<<<EB, 256>>>(src, dst);

    // ---- Layer 1 ----
    eler_k<<<NODE_WARP_BLOCKS, 256>>>((const __half*)p_feat1, al1, ar1, HD1, 32, 4);
    attn_alpha_k<<<NODE_WARP_BLOCKS, 256>>>();
    agg1_k<<<NODE_WARP_BLOCKS, 256>>>(b1);

    // ---- Layer 2 (padded to 192; A rows gathered through inverse_idx in GEMM) ----
    pad2_k<<<(KIN * HD2P + 255) / 256, 256>>>(W2, b2, al2, ar2);
    dim3 g2((N_NODES + 127) / 128, HD2P / 64);
    gemm_k<true><<<g2, 256, gsm>>>((const float*)p_out1, (const float*)p_W2p,
                                   (__half*)p_feat2, inv, N_NODES, HD2P);
    eler_k<<<NODE_WARP_BLOCKS, 256>>>((const __half*)p_feat2,
                                      (const float*)p_al2p, (const float*)p_ar2p, HD2P, 48, 6);
    attn_alpha_k<<<NODE_WARP_BLOCKS, 256>>>();
    agg2_k<<<NODE_WARP_BLOCKS, 256>>>(out);
}

// round 4
// speedup vs baseline: 2.0741x; 1.5971x over previous
#include <cuda_runtime.h>
#include <cuda_fp16.h>
#include <math.h>
#include <stdint.h>

#define N_NODES 100000
#define N_EDGES 1600000
#define KIN 128
#define HD1 128
#define HD2P 192   // padded 4*48 (real 4*47=188)

// ---------------- scratch (static device globals; no allocation) ----------------
__device__ int    g_counts[N_NODES + 1];
__device__ int    g_rowoff[N_NODES + 1];
__device__ int    g_bsums[128];
__device__ int    g_csr_src[N_EDGES];
__device__ __half g_feat1h[(size_t)N_NODES * HD1];
__device__ __half g_out1h [(size_t)N_NODES * HD1];
__device__ __half g_feat2h[(size_t)N_NODES * HD2P];
__device__ float  g_el[N_NODES * 4];
__device__ float  g_er[N_NODES * 4];
__device__ float  g_alpha[(size_t)N_EDGES * 4];
__device__ float  g_W2p[KIN * HD2P];
__device__ float  g_b2p[HD2P];
__device__ float  g_al2p[HD2P];
__device__ float  g_ar2p[HD2P];

// ---------------- CSR build ----------------
__global__ void zero_counts_k(int n) {
    int i = blockIdx.x * blockDim.x + threadIdx.x;
    if (i < n) g_counts[i] = 0;
}
__global__ void hist_k(const int* __restrict__ dst) {
    int e = blockIdx.x * blockDim.x + threadIdx.x;
    if (e < N_EDGES) atomicAdd(&g_counts[dst[e]], 1);
}
__global__ void scan_block_k(int n) {
    __shared__ int sh[1024];
    int i = blockIdx.x * 1024 + threadIdx.x;
    int v = (i < n) ? g_counts[i] : 0;
    sh[threadIdx.x] = v;
    __syncthreads();
    for (int off = 1; off < 1024; off <<= 1) {
        int t = (threadIdx.x >= off) ? sh[threadIdx.x - off] : 0;
        __syncthreads();
        sh[threadIdx.x] += t;
        __syncthreads();
    }
    if (i < n) g_rowoff[i] = sh[threadIdx.x] - v;  // exclusive
    if (threadIdx.x == 1023) g_bsums[blockIdx.x] = sh[1023];
}
__global__ void scan_sums_k(int nb) {
    __shared__ int sh[128];
    int t = threadIdx.x;
    int v = (t < nb) ? g_bsums[t] : 0;
    sh[t] = v;
    __syncthreads();
    for (int off = 1; off < 128; off <<= 1) {
        int u = (t >= off) ? sh[t - off] : 0;
        __syncthreads();
        sh[t] += u;
        __syncthreads();
    }
    if (t < nb) g_bsums[t] = sh[t] - v;  // exclusive
}
__global__ void scan_add_k(int n) {
    int i = blockIdx.x * 1024 + threadIdx.x;
    if (i < n) g_rowoff[i] += g_bsums[blockIdx.x];
}
__global__ void scatter_k(const int* __restrict__ src, const int* __restrict__ dst) {
    int e = blockIdx.x * blockDim.x + threadIdx.x;
    if (e >= N_EDGES) return;
    int d = dst[e];
    int pos = atomicAdd(&g_counts[d], 1);
    g_csr_src[g_rowoff[d] + pos] = src[e];
}

// ---------------- pad layer-2 params into 4x48 layout ----------------
__global__ void pad2_k(const float* __restrict__ W2, const float* __restrict__ b2,
                       const float* __restrict__ al2, const float* __restrict__ ar2) {
    int i = blockIdx.x * blockDim.x + threadIdx.x;
    if (i < KIN * HD2P) {
        int k = i / HD2P, c = i % HD2P;
        int h = c / 48, dd = c % 48;
        g_W2p[i] = (dd < 47) ? W2[k * 188 + h * 47 + dd] : 0.0f;
    }
    if (i < HD2P) {
        int h = i / 48, dd = i % 48;
        g_b2p[i]  = (dd < 47) ? b2 [h * 47 + dd] : 0.0f;
        g_al2p[i] = (dd < 47) ? al2[h * 47 + dd] : 0.0f;
        g_ar2p[i] = (dd < 47) ? ar2[h * 47 + dd] : 0.0f;
    }
}

// ---------------- tensor-core GEMM (mma.sync m16n8k16 f16->f32) ----------------
// C[nrows x kout](half) = A[nrows x 128] @ W[128 x kout](f32, converted to f16)
// Block: 256 thr (8 warps, 4x2), BM=128, BN=64, K=128 resident in smem.
#define LDA 136   // halves per A smem row (128 + 8 pad)
#define LDB 72    // halves per B smem row (64 + 8 pad)

__device__ __forceinline__ void ldsm_x4(uint32_t* r, uint32_t addr) {
    asm volatile("ldmatrix.sync.aligned.m8n8.x4.shared.b16 {%0,%1,%2,%3}, [%4];"
                 : "=r"(r[0]), "=r"(r[1]), "=r"(r[2]), "=r"(r[3]) : "r"(addr));
}
__device__ __forceinline__ void ldsm_x4t(uint32_t* r, uint32_t addr) {
    asm volatile("ldmatrix.sync.aligned.m8n8.x4.trans.shared.b16 {%0,%1,%2,%3}, [%4];"
                 : "=r"(r[0]), "=r"(r[1]), "=r"(r[2]), "=r"(r[3]) : "r"(addr));
}
__device__ __forceinline__ void mma16816(float* d, const uint32_t* a, uint32_t b0, uint32_t b1) {
    asm volatile("mma.sync.aligned.m16n8k16.row.col.f32.f16.f16.f32 "
                 "{%0,%1,%2,%3}, {%4,%5,%6,%7}, {%8,%9}, {%0,%1,%2,%3};"
                 : "+f"(d[0]), "+f"(d[1]), "+f"(d[2]), "+f"(d[3])
                 : "r"(a[0]), "r"(a[1]), "r"(a[2]), "r"(a[3]), "r"(b0), "r"(b1));
}

template <bool AHALF, bool IND>
__global__ void __launch_bounds__(256) gemm_tc_k(
    const void* __restrict__ Av, const float* __restrict__ W,
    __half* __restrict__ C, const int* __restrict__ ridx,
    int nrows, int kout)
{
    extern __shared__ __half smh[];
    __half* As = smh;                 // [128][LDA]
    __half* Bs = smh + 128 * LDA;     // [128][LDB]

    int t = threadIdx.x;
    int lane = t & 31;
    int w = t >> 5;
    int wm = w & 3;        // 0..3 -> 32-row slice
    int wn = w >> 2;       // 0..1 -> 32-col slice
    int rowb = blockIdx.x * 128;
    int colb = blockIdx.y * 64;

    // ---- load A tile into smem (fp16) ----
    if (AHALF) {
        const __half* A = (const __half*)Av;
        #pragma unroll
        for (int i = 0; i < 8; i++) {
            int flat = t + i * 256;          // 8-half chunks: 2048 total
            int rl = flat >> 4;              // 0..127
            int c8 = (flat & 15) << 3;       // 0..120
            int rg = rowb + rl;
            uint4 v = make_uint4(0u, 0u, 0u, 0u);
            if (rg < nrows) {
                int ra = IND ? ridx[rg] : rg;
                v = *reinterpret_cast<const uint4*>(A + (size_t)ra * KIN + c8);
            }
            *reinterpret_cast<uint4*>(As + rl * LDA + c8) = v;
        }
    } else {
        const float* A = (const float*)Av;
        #pragma unroll
        for (int i = 0; i < 16; i++) {
            int flat = t + i * 256;          // float4 chunks: 4096 total
            int rl = flat >> 5;              // 0..127
            int k4 = (flat & 31) << 2;       // 0..124
            int rg = rowb + rl;
            float4 v = make_float4(0.f, 0.f, 0.f, 0.f);
            if (rg < nrows) {
                int ra = IND ? ridx[rg] : rg;
                v = *reinterpret_cast<const float4*>(A + (size_t)ra * KIN + k4);
            }
            __half2 h01 = __floats2half2_rn(v.x, v.y);
            __half2 h23 = __floats2half2_rn(v.z, v.w);
            uint2 pk = make_uint2(*reinterpret_cast<unsigned int*>(&h01),
                                  *reinterpret_cast<unsigned int*>(&h23));
            *reinterpret_cast<uint2*>(As + rl * LDA + k4) = pk;
        }
    }
    // ---- load B tile (f32 -> f16) ----
    #pragma unroll
    for (int i = 0; i < 8; i++) {
        int flat = t + i * 256;              // 2048 float4 chunks
        int k  = flat >> 4;                  // 0..127
        int c4 = (flat & 15) << 2;           // 0..60
        float4 v = *reinterpret_cast<const float4*>(W + (size_t)k * kout + colb + c4);
        __half2 h01 = __floats2half2_rn(v.x, v.y);
        __half2 h23 = __floats2half2_rn(v.z, v.w);
        uint2 pk = make_uint2(*reinterpret_cast<unsigned int*>(&h01),
                              *reinterpret_cast<unsigned int*>(&h23));
        *reinterpret_cast<uint2*>(Bs + k * LDB + c4) = pk;
    }
    __syncthreads();

    uint32_t sA = (uint32_t)__cvta_generic_to_shared(As);
    uint32_t sB = (uint32_t)__cvta_generic_to_shared(Bs);
    // ldmatrix lane address bases (bytes)
    uint32_t aBase = sA + 2u * ((wm * 32 + (lane & 15)) * LDA + (lane >> 4) * 8);
    uint32_t bBase = sB + 2u * ((lane & 15) * LDB + wn * 32 + (lane >> 4) * 8);

    float d[2][4][4];
    #pragma unroll
    for (int mt = 0; mt < 2; mt++)
        #pragma unroll
        for (int nt = 0; nt < 4; nt++)
            #pragma unroll
            for (int q = 0; q < 4; q++) d[mt][nt][q] = 0.f;

    #pragma unroll
    for (int ks = 0; ks < 8; ks++) {
        uint32_t a0[4], a1[4], b0[4], b1[4];
        ldsm_x4 (a0, aBase + 2u * (ks * 16));
        ldsm_x4 (a1, aBase + 2u * (16 * LDA + ks * 16));
        ldsm_x4t(b0, bBase + 2u * (ks * 16 * LDB));
        ldsm_x4t(b1, bBase + 2u * (ks * 16 * LDB + 16));
        mma16816(d[0][0], a0, b0[0], b0[1]);
        mma16816(d[0][1], a0, b0[2], b0[3]);
        mma16816(d[0][2], a0, b1[0], b1[1]);
        mma16816(d[0][3], a0, b1[2], b1[3]);
        mma16816(d[1][0], a1, b0[0], b0[1]);
        mma16816(d[1][1], a1, b0[2], b0[3]);
        mma16816(d[1][2], a1, b1[0], b1[1]);
        mma16816(d[1][3], a1, b1[2], b1[3]);
    }

    // ---- epilogue: fp32 acc -> half2 stores ----
    int rbase = rowb + wm * 32 + (lane >> 2);
    int cbase = colb + wn * 32 + ((lane & 3) << 1);
    #pragma unroll
    for (int mt = 0; mt < 2; mt++) {
        int r0 = rbase + mt * 16;
        #pragma unroll
        for (int nt = 0; nt < 4; nt++) {
            int c0 = cbase + nt * 8;
            if (r0 < nrows) {
                __half2 h = __floats2half2_rn(d[mt][nt][0], d[mt][nt][1]);
                *reinterpret_cast<__half2*>(C + (size_t)r0 * kout + c0) = h;
            }
            if (r0 + 8 < nrows) {
                __half2 h = __floats2half2_rn(d[mt][nt][2], d[mt][nt][3]);
                *reinterpret_cast<__half2*>(C + (size_t)(r0 + 8) * kout + c0) = h;
            }
        }
    }
}

// ---------------- el/er: per-node per-head attention dots (half feats) ----------------
__global__ void eler_k(const __half* __restrict__ feat,
                       const float* __restrict__ al, const float* __restrict__ ar,
                       int hd, int dpad, int dpl)
{
    int w = (blockIdx.x * blockDim.x + threadIdx.x) >> 5;
    int lane = threadIdx.x & 31;
    if (w >= N_NODES) return;
    int h = lane >> 3;
    const __half* f = feat + (size_t)w * hd + lane * dpl;
    const float* alh = al + h * dpad + (lane & 7) * dpl;
    const float* arh = ar + h * dpad + (lane & 7) * dpl;
    float accL = 0.f, accR = 0.f;
    for (int q = 0; q < dpl; q++) {
        float v = __half2float(f[q]);
        accL = fmaf(v, alh[q], accL);
        accR = fmaf(v, arh[q], accR);
    }
    #pragma unroll
    for (int off = 4; off; off >>= 1) {
        accL += __shfl_xor_sync(0xffffffffu, accL, off);
        accR += __shfl_xor_sync(0xffffffffu, accR, off);
    }
    float l0 = __shfl_sync(0xffffffffu, accL, 0);
    float l1 = __shfl_sync(0xffffffffu, accL, 8);
    float l2 = __shfl_sync(0xffffffffu, accL, 16);
    float l3 = __shfl_sync(0xffffffffu, accL, 24);
    float r0 = __shfl_sync(0xffffffffu, accR, 0);
    float r1 = __shfl_sync(0xffffffffu, accR, 8);
    float r2 = __shfl_sync(0xffffffffu, accR, 16);
    float r3 = __shfl_sync(0xffffffffu, accR, 24);
    if (lane == 0) {
        *reinterpret_cast<float4*>(g_el + (size_t)w * 4) = make_float4(l0, l1, l2, l3);
        *reinterpret_cast<float4*>(g_er + (size_t)w * 4) = make_float4(r0, r1, r2, r3);
    }
}

// ---------------- fused softmax stats + alpha (two passes over CSR edges) ----------------
__global__ void attn_alpha_k()
{
    int w = (blockIdx.x * blockDim.x + threadIdx.x) >> 5;
    int lane = threadIdx.x & 31;
    if (w >= N_NODES) return;
    int s0 = g_rowoff[w], e0 = g_rowoff[w + 1];
    if (s0 == e0) return;
    float4 erd = *reinterpret_cast<const float4*>(g_er + (size_t)w * 4);

    float mx[4] = {-1e30f, -1e30f, -1e30f, -1e30f};
    float sm[4] = {0.f, 0.f, 0.f, 0.f};
    for (int i = s0 + lane; i < e0; i += 32) {
        int sn = g_csr_src[i];
        float4 eL = *reinterpret_cast<const float4*>(g_el + (size_t)sn * 4);
        float ev[4] = {eL.x + erd.x, eL.y + erd.y, eL.z + erd.z, eL.w + erd.w};
        #pragma unroll
        for (int h = 0; h < 4; h++) {
            float e = ev[h];
            e = fmaxf(e, 0.2f * e);               // LeakyReLU
            float nm = fmaxf(mx[h], e);
            sm[h] = sm[h] * __expf(mx[h] - nm) + __expf(e - nm);
            mx[h] = nm;
        }
    }
    #pragma unroll
    for (int off = 16; off; off >>= 1) {
        #pragma unroll
        for (int h = 0; h < 4; h++) {
            float om = __shfl_xor_sync(0xffffffffu, mx[h], off);
            float os = __shfl_xor_sync(0xffffffffu, sm[h], off);
            float nm = fmaxf(mx[h], om);
            sm[h] = sm[h] * __expf(mx[h] - nm) + os * __expf(om - nm);
            mx[h] = nm;
        }
    }
    float iv[4];
    #pragma unroll
    for (int h = 0; h < 4; h++) iv[h] = 1.0f / fmaxf(sm[h], 1e-9f);

    for (int i = s0 + lane; i < e0; i += 32) {
        int sn = g_csr_src[i];
        float4 eL = *reinterpret_cast<const float4*>(g_el + (size_t)sn * 4);
        float4 a;
        float v;
        v = eL.x + erd.x; v = fmaxf(v, 0.2f * v); a.x = __expf(v - mx[0]) * iv[0];
        v = eL.y + erd.y; v = fmaxf(v, 0.2f * v); a.y = __expf(v - mx[1]) * iv[1];
        v = eL.z + erd.z; v = fmaxf(v, 0.2f * v); a.z = __expf(v - mx[2]) * iv[2];
        v = eL.w + erd.w; v = fmaxf(v, 0.2f * v); a.w = __expf(v - mx[3]) * iv[3];
        *reinterpret_cast<float4*>(g_alpha + (size_t)i * 4) = a;
    }
}

// ---------------- layer-1 aggregation: warp per node, half feats, ELU + bias, half out ----------------
__global__ void agg1_k(const float* __restrict__ b1)
{
    int w = (blockIdx.x * blockDim.x + threadIdx.x) >> 5;
    int lane = threadIdx.x & 31;
    if (w >= N_NODES) return;
    int s0 = g_rowoff[w], e0 = g_rowoff[w + 1];
    int hd = lane >> 3;
    const uint2* fv = reinterpret_cast<const uint2*>(g_feat1h);  // 32 uint2 per row
    float4 acc = make_float4(0.f, 0.f, 0.f, 0.f);
    int i = s0;
    for (; i + 1 < e0; i += 2) {
        int s1 = g_csr_src[i];
        int s2 = g_csr_src[i + 1];
        float a1 = g_alpha[(size_t)i * 4 + hd];
        float a2 = g_alpha[(size_t)(i + 1) * 4 + hd];
        uint2 u1 = fv[(size_t)s1 * 32 + lane];
        uint2 u2 = fv[(size_t)s2 * 32 + lane];
        float2 f10 = __half22float2(*reinterpret_cast<__half2*>(&u1.x));
        float2 f11 = __half22float2(*reinterpret_cast<__half2*>(&u1.y));
        float2 f20 = __half22float2(*reinterpret_cast<__half2*>(&u2.x));
        float2 f21 = __half22float2(*reinterpret_cast<__half2*>(&u2.y));
        acc.x = fmaf(f10.x, a1, acc.x); acc.y = fmaf(f10.y, a1, acc.y);
        acc.z = fmaf(f11.x, a1, acc.z); acc.w = fmaf(f11.y, a1, acc.w);
        acc.x = fmaf(f20.x, a2, acc.x); acc.y = fmaf(f20.y, a2, acc.y);
        acc.z = fmaf(f21.x, a2, acc.z); acc.w = fmaf(f21.y, a2, acc.w);
    }
    if (i < e0) {
        int s1 = g_csr_src[i];
        float a1 = g_alpha[(size_t)i * 4 + hd];
        uint2 u1 = fv[(size_t)s1 * 32 + lane];
        float2 f10 = __half22float2(*reinterpret_cast<__half2*>(&u1.x));
        float2 f11 = __half22float2(*reinterpret_cast<__half2*>(&u1.y));
        acc.x = fmaf(f10.x, a1, acc.x); acc.y = fmaf(f10.y, a1, acc.y);
        acc.z = fmaf(f11.x, a1, acc.z); acc.w = fmaf(f11.y, a1, acc.w);
    }
    float4 bb = *reinterpret_cast<const float4*>(b1 + lane * 4);
    acc.x += bb.x; acc.y += bb.y; acc.z += bb.z; acc.w += bb.w;
    acc.x = (acc.x > 0.f) ? acc.x : (__expf(acc.x) - 1.f);
    acc.y = (acc.y > 0.f) ? acc.y : (__expf(acc.y) - 1.f);
    acc.z = (acc.z > 0.f) ? acc.z : (__expf(acc.z) - 1.f);
    acc.w = (acc.w > 0.f) ? acc.w : (__expf(acc.w) - 1.f);
    __half2 h01 = __floats2half2_rn(acc.x, acc.y);
    __half2 h23 = __floats2half2_rn(acc.z, acc.w);
    uint2 pk = make_uint2(*reinterpret_cast<unsigned int*>(&h01),
                          *reinterpret_cast<unsigned int*>(&h23));
    *reinterpret_cast<uint2*>(g_out1h + (size_t)w * HD1 + lane * 4) = pk;
}

// ---------------- layer-2 aggregation: warp per node, padded half feats, bias + head-mean ----------------
__global__ void agg2_k(float* __restrict__ out)
{
    __shared__ float sbuf[8][HD2P];
    int wl = threadIdx.x >> 5;
    int w = blockIdx.x * 8 + wl;
    int lane = threadIdx.x & 31;
    if (w >= N_NODES) return;
    int s0 = g_rowoff[w], e0 = g_rowoff[w + 1];
    int h = lane >> 3;
    const unsigned int* fp = reinterpret_cast<const unsigned int*>(g_feat2h);  // 96 uints per row
    int lb = lane * 3;
    float acc[6] = {0.f, 0.f, 0.f, 0.f, 0.f, 0.f};
    for (int i = s0; i < e0; i++) {
        int sn = g_csr_src[i];
        float4 a4 = *reinterpret_cast<const float4*>(g_alpha + (size_t)i * 4);
        float a = (h < 2) ? (h == 0 ? a4.x : a4.y) : (h == 2 ? a4.z : a4.w);
        const unsigned int* f = fp + (size_t)sn * 96 + lb;
        unsigned int u0 = f[0], u1 = f[1], u2 = f[2];
        float2 p0 = __half22float2(*reinterpret_cast<__half2*>(&u0));
        float2 p1 = __half22float2(*reinterpret_cast<__half2*>(&u1));
        float2 p2 = __half22float2(*reinterpret_cast<__half2*>(&u2));
        acc[0] = fmaf(p0.x, a, acc[0]); acc[1] = fmaf(p0.y, a, acc[1]);
        acc[2] = fmaf(p1.x, a, acc[2]); acc[3] = fmaf(p1.y, a, acc[3]);
        acc[4] = fmaf(p2.x, a, acc[4]); acc[5] = fmaf(p2.y, a, acc[5]);
    }
    int db = lane * 6;
    #pragma unroll
    for (int q = 0; q < 6; q++)
        sbuf[wl][db + q] = acc[q] + g_b2p[db + q];
    __syncwarp();
    for (int c = lane; c < 47; c += 32) {
        float v = sbuf[wl][c] + sbuf[wl][48 + c] + sbuf[wl][96 + c] + sbuf[wl][144 + c];
        out[(size_t)w * 47 + c] = 0.25f * v;
    }
}

// ---------------- host launcher ----------------
extern "C" void kernel_launch(void* const* d_in, const int* in_sizes, int n_in,
                              void* d_out, int out_size)
{
    const float* x   = (const float*)d_in[0];
    const int*   src = (const int*)  d_in[1];
    const int*   dst = (const int*)  d_in[2];
    const int*   inv = (const int*)  d_in[3];
    const float* W1  = (const float*)d_in[4];
    const float* al1 = (const float*)d_in[5];
    const float* ar1 = (const float*)d_in[6];
    const float* b1  = (const float*)d_in[7];
    const float* W2  = (const float*)d_in[8];
    const float* al2 = (const float*)d_in[9];
    const float* ar2 = (const float*)d_in[10];
    const float* b2  = (const float*)d_in[11];
    float* out = (float*)d_out;
    (void)in_sizes; (void)n_in; (void)out_size;

    void *p_feat1 = nullptr, *p_out1 = nullptr, *p_feat2 = nullptr;
    void *p_W2p = nullptr, *p_al2p = nullptr, *p_ar2p = nullptr;
    cudaGetSymbolAddress(&p_feat1, g_feat1h);
    cudaGetSymbolAddress(&p_out1,  g_out1h);
    cudaGetSymbolAddress(&p_feat2, g_feat2h);
    cudaGetSymbolAddress(&p_W2p,   g_W2p);
    cudaGetSymbolAddress(&p_al2p,  g_al2p);
    cudaGetSymbolAddress(&p_ar2p,  g_ar2p);

    const int NP1 = N_NODES + 1;
    const int SCAN_BLOCKS = (NP1 + 1023) / 1024;
    const int EB = (N_EDGES + 255) / 256;
    const int NODE_WARP_BLOCKS = (N_NODES + 7) / 8;

    size_t gsm = (size_t)(128 * LDA + 128 * LDB) * sizeof(__half);  // 53248 B
    cudaFuncSetAttribute((const void*)gemm_tc_k<false, false>, cudaFuncAttributeMaxDynamicSharedMemorySize, (int)gsm);
    cudaFuncSetAttribute((const void*)gemm_tc_k<true, true>,   cudaFuncAttributeMaxDynamicSharedMemorySize, (int)gsm);

    // CSR build
    zero_counts_k<<<(NP1 + 255) / 256, 256>>>(NP1);
    hist_k<<<EB, 256>>>(dst);
    scan_block_k<<<SCAN_BLOCKS, 1024>>>(NP1);
    scan_sums_k<<<1, 128>>>(SCAN_BLOCKS);
    scan_add_k<<<SCAN_BLOCKS, 1024>>>(NP1);

    // GEMM1 (fp32 A converted in-kernel)
    dim3 g1((N_NODES + 127) / 128, HD1 / 64);
    gemm_tc_k<false, false><<<g1, 256, gsm>>>(x, W1, (__half*)p_feat1, nullptr, N_NODES, HD1);

    // finish CSR
    zero_counts_k<<<(NP1 + 255) / 256, 256>>>(NP1);
    scatter_k<<<EB, 256>>>(src, dst);

    // ---- Layer 1 ----
    eler_k<<<NODE_WARP_BLOCKS, 256>>>((const __half*)p_feat1, al1, ar1, HD1, 32, 4);
    attn_alpha_k<<<NODE_WARP_BLOCKS, 256>>>();
    agg1_k<<<NODE_WARP_BLOCKS, 256>>>(b1);

    // ---- Layer 2 (padded to 192; fp16 A gathered through inverse_idx) ----
    pad2_k<<<(KIN * HD2P + 255) / 256, 256>>>(W2, b2, al2, ar2);
    dim3 g2((N_NODES + 127) / 128, HD2P / 64);
    gemm_tc_k<true, true><<<g2, 256, gsm>>>(p_out1, (const float*)p_W2p,
                                            (__half*)p_feat2, inv, N_NODES, HD2P);
    eler_k<<<NODE_WARP_BLOCKS, 256>>>((const __half*)p_feat2,
                                      (const float*)p_al2p, (const float*)p_ar2p, HD2P, 48, 6);
    attn_alpha_k<<<NODE_WARP_BLOCKS, 256>>>();
    agg2_k<<<NODE_WARP_BLOCKS, 256>>>(out);
}

// round 5
// speedup vs baseline: 2.6404x; 1.2730x over previous
#include <cuda_runtime.h>
#include <cuda_fp16.h>
#include <math.h>
#include <stdint.h>

#define N_NODES 100000
#define N_EDGES 1600000
#define KIN 128
#define HD1 128
#define HD2P 192   // padded 4*48 (real 4*47=188)

// ---------------- scratch (static device globals; no allocation) ----------------
__device__ int    g_counts[N_NODES + 1];
__device__ int    g_rowoff[N_NODES + 1];
__device__ int    g_bsums[128];
__device__ int    g_csr_src[N_EDGES];
__device__ __half g_feat1h[(size_t)N_NODES * HD1];
__device__ __half g_out1h [(size_t)N_NODES * HD1];
__device__ __half g_feat2h[(size_t)N_NODES * HD2P];
__device__ float  g_el[N_NODES * 4];
__device__ float  g_er[N_NODES * 4];
__device__ float  g_alpha[(size_t)N_EDGES * 4];   // UNNORMALIZED exp values
__device__ float  g_W2p[KIN * HD2P];
__device__ float  g_b2p[HD2P];
__device__ float  g_al2p[HD2P];
__device__ float  g_ar2p[HD2P];

// ---------------- CSR build ----------------
__global__ void zero_counts_k(int n) {
    int i = blockIdx.x * blockDim.x + threadIdx.x;
    if (i < n) g_counts[i] = 0;
}
__global__ void hist_k(const int* __restrict__ dst) {
    int e = blockIdx.x * blockDim.x + threadIdx.x;
    if (e < N_EDGES) atomicAdd(&g_counts[dst[e]], 1);
}
__global__ void scan_block_k(int n) {
    __shared__ int sh[1024];
    int i = blockIdx.x * 1024 + threadIdx.x;
    int v = (i < n) ? g_counts[i] : 0;
    sh[threadIdx.x] = v;
    __syncthreads();
    for (int off = 1; off < 1024; off <<= 1) {
        int t = (threadIdx.x >= off) ? sh[threadIdx.x - off] : 0;
        __syncthreads();
        sh[threadIdx.x] += t;
        __syncthreads();
    }
    if (i < n) g_rowoff[i] = sh[threadIdx.x] - v;  // exclusive
    if (threadIdx.x == 1023) g_bsums[blockIdx.x] = sh[1023];
}
__global__ void scan_sums_k(int nb) {
    __shared__ int sh[128];
    int t = threadIdx.x;
    int v = (t < nb) ? g_bsums[t] : 0;
    sh[t] = v;
    __syncthreads();
    for (int off = 1; off < 128; off <<= 1) {
        int u = (t >= off) ? sh[t - off] : 0;
        __syncthreads();
        sh[t] += u;
        __syncthreads();
    }
    if (t < nb) g_bsums[t] = sh[t] - v;  // exclusive
}
__global__ void scan_add_k(int n) {
    int i = blockIdx.x * 1024 + threadIdx.x;
    if (i < n) g_rowoff[i] += g_bsums[blockIdx.x];
}
__global__ void scatter_k(const int* __restrict__ src, const int* __restrict__ dst) {
    int e = blockIdx.x * blockDim.x + threadIdx.x;
    if (e >= N_EDGES) return;
    int d = dst[e];
    int pos = atomicAdd(&g_counts[d], 1);
    g_csr_src[g_rowoff[d] + pos] = src[e];
}

// ---------------- pad layer-2 params into 4x48 layout ----------------
__global__ void pad2_k(const float* __restrict__ W2, const float* __restrict__ b2,
                       const float* __restrict__ al2, const float* __restrict__ ar2) {
    int i = blockIdx.x * blockDim.x + threadIdx.x;
    if (i < KIN * HD2P) {
        int k = i / HD2P, c = i % HD2P;
        int h = c / 48, dd = c % 48;
        g_W2p[i] = (dd < 47) ? W2[k * 188 + h * 47 + dd] : 0.0f;
    }
    if (i < HD2P) {
        int h = i / 48, dd = i % 48;
        g_b2p[i]  = (dd < 47) ? b2 [h * 47 + dd] : 0.0f;
        g_al2p[i] = (dd < 47) ? al2[h * 47 + dd] : 0.0f;
        g_ar2p[i] = (dd < 47) ? ar2[h * 47 + dd] : 0.0f;
    }
}

// ---------------- tensor-core GEMM (mma.sync m16n8k16 f16->f32) ----------------
#define LDA 136
#define LDB 72

__device__ __forceinline__ void ldsm_x4(uint32_t* r, uint32_t addr) {
    asm volatile("ldmatrix.sync.aligned.m8n8.x4.shared.b16 {%0,%1,%2,%3}, [%4];"
                 : "=r"(r[0]), "=r"(r[1]), "=r"(r[2]), "=r"(r[3]) : "r"(addr));
}
__device__ __forceinline__ void ldsm_x4t(uint32_t* r, uint32_t addr) {
    asm volatile("ldmatrix.sync.aligned.m8n8.x4.trans.shared.b16 {%0,%1,%2,%3}, [%4];"
                 : "=r"(r[0]), "=r"(r[1]), "=r"(r[2]), "=r"(r[3]) : "r"(addr));
}
__device__ __forceinline__ void mma16816(float* d, const uint32_t* a, uint32_t b0, uint32_t b1) {
    asm volatile("mma.sync.aligned.m16n8k16.row.col.f32.f16.f16.f32 "
                 "{%0,%1,%2,%3}, {%4,%5,%6,%7}, {%8,%9}, {%0,%1,%2,%3};"
                 : "+f"(d[0]), "+f"(d[1]), "+f"(d[2]), "+f"(d[3])
                 : "r"(a[0]), "r"(a[1]), "r"(a[2]), "r"(a[3]), "r"(b0), "r"(b1));
}

template <bool AHALF, bool IND>
__global__ void __launch_bounds__(256) gemm_tc_k(
    const void* __restrict__ Av, const float* __restrict__ W,
    __half* __restrict__ C, const int* __restrict__ ridx,
    int nrows, int kout)
{
    extern __shared__ __half smh[];
    __half* As = smh;                 // [128][LDA]
    __half* Bs = smh + 128 * LDA;     // [128][LDB]

    int t = threadIdx.x;
    int lane = t & 31;
    int w = t >> 5;
    int wm = w & 3;
    int wn = w >> 2;
    int rowb = blockIdx.x * 128;
    int colb = blockIdx.y * 64;

    if (AHALF) {
        const __half* A = (const __half*)Av;
        #pragma unroll
        for (int i = 0; i < 8; i++) {
            int flat = t + i * 256;
            int rl = flat >> 4;
            int c8 = (flat & 15) << 3;
            int rg = rowb + rl;
            uint4 v = make_uint4(0u, 0u, 0u, 0u);
            if (rg < nrows) {
                int ra = IND ? ridx[rg] : rg;
                v = *reinterpret_cast<const uint4*>(A + (size_t)ra * KIN + c8);
            }
            *reinterpret_cast<uint4*>(As + rl * LDA + c8) = v;
        }
    } else {
        const float* A = (const float*)Av;
        #pragma unroll
        for (int i = 0; i < 16; i++) {
            int flat = t + i * 256;
            int rl = flat >> 5;
            int k4 = (flat & 31) << 2;
            int rg = rowb + rl;
            float4 v = make_float4(0.f, 0.f, 0.f, 0.f);
            if (rg < nrows) {
                int ra = IND ? ridx[rg] : rg;
                v = *reinterpret_cast<const float4*>(A + (size_t)ra * KIN + k4);
            }
            __half2 h01 = __floats2half2_rn(v.x, v.y);
            __half2 h23 = __floats2half2_rn(v.z, v.w);
            uint2 pk = make_uint2(*reinterpret_cast<unsigned int*>(&h01),
                                  *reinterpret_cast<unsigned int*>(&h23));
            *reinterpret_cast<uint2*>(As + rl * LDA + k4) = pk;
        }
    }
    #pragma unroll
    for (int i = 0; i < 8; i++) {
        int flat = t + i * 256;
        int k  = flat >> 4;
        int c4 = (flat & 15) << 2;
        float4 v = *reinterpret_cast<const float4*>(W + (size_t)k * kout + colb + c4);
        __half2 h01 = __floats2half2_rn(v.x, v.y);
        __half2 h23 = __floats2half2_rn(v.z, v.w);
        uint2 pk = make_uint2(*reinterpret_cast<unsigned int*>(&h01),
                              *reinterpret_cast<unsigned int*>(&h23));
        *reinterpret_cast<uint2*>(Bs + k * LDB + c4) = pk;
    }
    __syncthreads();

    uint32_t sA = (uint32_t)__cvta_generic_to_shared(As);
    uint32_t sB = (uint32_t)__cvta_generic_to_shared(Bs);
    uint32_t aBase = sA + 2u * ((wm * 32 + (lane & 15)) * LDA + (lane >> 4) * 8);
    uint32_t bBase = sB + 2u * ((lane & 15) * LDB + wn * 32 + (lane >> 4) * 8);

    float d[2][4][4];
    #pragma unroll
    for (int mt = 0; mt < 2; mt++)
        #pragma unroll
        for (int nt = 0; nt < 4; nt++)
            #pragma unroll
            for (int q = 0; q < 4; q++) d[mt][nt][q] = 0.f;

    #pragma unroll
    for (int ks = 0; ks < 8; ks++) {
        uint32_t a0[4], a1[4], b0[4], b1[4];
        ldsm_x4 (a0, aBase + 2u * (ks * 16));
        ldsm_x4 (a1, aBase + 2u * (16 * LDA + ks * 16));
        ldsm_x4t(b0, bBase + 2u * (ks * 16 * LDB));
        ldsm_x4t(b1, bBase + 2u * (ks * 16 * LDB + 16));
        mma16816(d[0][0], a0, b0[0], b0[1]);
        mma16816(d[0][1], a0, b0[2], b0[3]);
        mma16816(d[0][2], a0, b1[0], b1[1]);
        mma16816(d[0][3], a0, b1[2], b1[3]);
        mma16816(d[1][0], a1, b0[0], b0[1]);
        mma16816(d[1][1], a1, b0[2], b0[3]);
        mma16816(d[1][2], a1, b1[0], b1[1]);
        mma16816(d[1][3], a1, b1[2], b1[3]);
    }

    int rbase = rowb + wm * 32 + (lane >> 2);
    int cbase = colb + wn * 32 + ((lane & 3) << 1);
    #pragma unroll
    for (int mt = 0; mt < 2; mt++) {
        int r0 = rbase + mt * 16;
        #pragma unroll
        for (int nt = 0; nt < 4; nt++) {
            int c0 = cbase + nt * 8;
            if (r0 < nrows) {
                __half2 h = __floats2half2_rn(d[mt][nt][0], d[mt][nt][1]);
                *reinterpret_cast<__half2*>(C + (size_t)r0 * kout + c0) = h;
            }
            if (r0 + 8 < nrows) {
                __half2 h = __floats2half2_rn(d[mt][nt][2], d[mt][nt][3]);
                *reinterpret_cast<__half2*>(C + (size_t)(r0 + 8) * kout + c0) = h;
            }
        }
    }
}

// ---------------- el/er: per-node per-head attention dots (half feats) ----------------
__global__ void eler_k(const __half* __restrict__ feat,
                       const float* __restrict__ al, const float* __restrict__ ar,
                       int hd, int dpad, int dpl)
{
    int w = (blockIdx.x * blockDim.x + threadIdx.x) >> 5;
    int lane = threadIdx.x & 31;
    if (w >= N_NODES) return;
    int h = lane >> 3;
    const __half* f = feat + (size_t)w * hd + lane * dpl;
    const float* alh = al + h * dpad + (lane & 7) * dpl;
    const float* arh = ar + h * dpad + (lane & 7) * dpl;
    float accL = 0.f, accR = 0.f;
    for (int q = 0; q < dpl; q++) {
        float v = __half2float(f[q]);
        accL = fmaf(v, alh[q], accL);
        accR = fmaf(v, arh[q], accR);
    }
    #pragma unroll
    for (int off = 4; off; off >>= 1) {
        accL += __shfl_xor_sync(0xffffffffu, accL, off);
        accR += __shfl_xor_sync(0xffffffffu, accR, off);
    }
    float l0 = __shfl_sync(0xffffffffu, accL, 0);
    float l1 = __shfl_sync(0xffffffffu, accL, 8);
    float l2 = __shfl_sync(0xffffffffu, accL, 16);
    float l3 = __shfl_sync(0xffffffffu, accL, 24);
    float r0 = __shfl_sync(0xffffffffu, accR, 0);
    float r1 = __shfl_sync(0xffffffffu, accR, 8);
    float r2 = __shfl_sync(0xffffffffu, accR, 16);
    float r3 = __shfl_sync(0xffffffffu, accR, 24);
    if (lane == 0) {
        *reinterpret_cast<float4*>(g_el + (size_t)w * 4) = make_float4(l0, l1, l2, l3);
        *reinterpret_cast<float4*>(g_er + (size_t)w * 4) = make_float4(r0, r1, r2, r3);
    }
}

// ---------------- fused attention + aggregation, layer 1 ----------------
// Phase 1: ex = exp(leaky(el+er)) per edge (4 MUFU/edge, no max-sub),
//          write unnormalized ex to g_alpha, accumulate per-head sums.
// Phase 2: aggregate feat1 rows weighted by ex, scale by 1/sum, bias + ELU.
__global__ void attn_agg1_k(const float* __restrict__ b1)
{
    int w = (blockIdx.x * blockDim.x + threadIdx.x) >> 5;
    int lane = threadIdx.x & 31;
    if (w >= N_NODES) return;
    int s0 = g_rowoff[w], e0 = g_rowoff[w + 1];
    float4 erd = *reinterpret_cast<const float4*>(g_er + (size_t)w * 4);

    float sm0 = 0.f, sm1 = 0.f, sm2 = 0.f, sm3 = 0.f;
    for (int i = s0 + lane; i < e0; i += 32) {
        int sn = g_csr_src[i];
        float4 eL = *reinterpret_cast<const float4*>(g_el + (size_t)sn * 4);
        float4 ex;
        float v;
        v = eL.x + erd.x; v = fmaxf(v, 0.2f * v); ex.x = __expf(v); sm0 += ex.x;
        v = eL.y + erd.y; v = fmaxf(v, 0.2f * v); ex.y = __expf(v); sm1 += ex.y;
        v = eL.z + erd.z; v = fmaxf(v, 0.2f * v); ex.z = __expf(v); sm2 += ex.z;
        v = eL.w + erd.w; v = fmaxf(v, 0.2f * v); ex.w = __expf(v); sm3 += ex.w;
        *reinterpret_cast<float4*>(g_alpha + (size_t)i * 4) = ex;
    }
    #pragma unroll
    for (int off = 16; off; off >>= 1) {
        sm0 += __shfl_xor_sync(0xffffffffu, sm0, off);
        sm1 += __shfl_xor_sync(0xffffffffu, sm1, off);
        sm2 += __shfl_xor_sync(0xffffffffu, sm2, off);
        sm3 += __shfl_xor_sync(0xffffffffu, sm3, off);
    }
    int hd = lane >> 3;
    float smh = (hd == 0) ? sm0 : (hd == 1) ? sm1 : (hd == 2) ? sm2 : sm3;
    float ivh = 1.0f / fmaxf(smh, 1e-9f);
    __syncwarp();

    const uint2* fv = reinterpret_cast<const uint2*>(g_feat1h);
    float4 acc = make_float4(0.f, 0.f, 0.f, 0.f);
    int i = s0;
    for (; i + 1 < e0; i += 2) {
        int s1 = g_csr_src[i];
        int s2 = g_csr_src[i + 1];
        float a1 = g_alpha[(size_t)i * 4 + hd];
        float a2 = g_alpha[(size_t)(i + 1) * 4 + hd];
        uint2 u1 = fv[(size_t)s1 * 32 + lane];
        uint2 u2 = fv[(size_t)s2 * 32 + lane];
        float2 f10 = __half22float2(*reinterpret_cast<__half2*>(&u1.x));
        float2 f11 = __half22float2(*reinterpret_cast<__half2*>(&u1.y));
        float2 f20 = __half22float2(*reinterpret_cast<__half2*>(&u2.x));
        float2 f21 = __half22float2(*reinterpret_cast<__half2*>(&u2.y));
        acc.x = fmaf(f10.x, a1, acc.x); acc.y = fmaf(f10.y, a1, acc.y);
        acc.z = fmaf(f11.x, a1, acc.z); acc.w = fmaf(f11.y, a1, acc.w);
        acc.x = fmaf(f20.x, a2, acc.x); acc.y = fmaf(f20.y, a2, acc.y);
        acc.z = fmaf(f21.x, a2, acc.z); acc.w = fmaf(f21.y, a2, acc.w);
    }
    if (i < e0) {
        int s1 = g_csr_src[i];
        float a1 = g_alpha[(size_t)i * 4 + hd];
        uint2 u1 = fv[(size_t)s1 * 32 + lane];
        float2 f10 = __half22float2(*reinterpret_cast<__half2*>(&u1.x));
        float2 f11 = __half22float2(*reinterpret_cast<__half2*>(&u1.y));
        acc.x = fmaf(f10.x, a1, acc.x); acc.y = fmaf(f10.y, a1, acc.y);
        acc.z = fmaf(f11.x, a1, acc.z); acc.w = fmaf(f11.y, a1, acc.w);
    }
    float4 bb = *reinterpret_cast<const float4*>(b1 + lane * 4);
    acc.x = fmaf(acc.x, ivh, bb.x);
    acc.y = fmaf(acc.y, ivh, bb.y);
    acc.z = fmaf(acc.z, ivh, bb.z);
    acc.w = fmaf(acc.w, ivh, bb.w);
    acc.x = (acc.x > 0.f) ? acc.x : (__expf(acc.x) - 1.f);
    acc.y = (acc.y > 0.f) ? acc.y : (__expf(acc.y) - 1.f);
    acc.z = (acc.z > 0.f) ? acc.z : (__expf(acc.z) - 1.f);
    acc.w = (acc.w > 0.f) ? acc.w : (__expf(acc.w) - 1.f);
    __half2 h01 = __floats2half2_rn(acc.x, acc.y);
    __half2 h23 = __floats2half2_rn(acc.z, acc.w);
    uint2 pk = make_uint2(*reinterpret_cast<unsigned int*>(&h01),
                          *reinterpret_cast<unsigned int*>(&h23));
    *reinterpret_cast<uint2*>(g_out1h + (size_t)w * HD1 + lane * 4) = pk;
}

// ---------------- fused attention + aggregation, layer 2 (padded 4x48, head-mean) ----------------
__global__ void attn_agg2_k(float* __restrict__ out)
{
    __shared__ float sbuf[8][HD2P];
    int wl = threadIdx.x >> 5;
    int w = blockIdx.x * 8 + wl;
    int lane = threadIdx.x & 31;
    if (w >= N_NODES) return;
    int s0 = g_rowoff[w], e0 = g_rowoff[w + 1];
    float4 erd = *reinterpret_cast<const float4*>(g_er + (size_t)w * 4);

    float sm0 = 0.f, sm1 = 0.f, sm2 = 0.f, sm3 = 0.f;
    for (int i = s0 + lane; i < e0; i += 32) {
        int sn = g_csr_src[i];
        float4 eL = *reinterpret_cast<const float4*>(g_el + (size_t)sn * 4);
        float4 ex;
        float v;
        v = eL.x + erd.x; v = fmaxf(v, 0.2f * v); ex.x = __expf(v); sm0 += ex.x;
        v = eL.y + erd.y; v = fmaxf(v, 0.2f * v); ex.y = __expf(v); sm1 += ex.y;
        v = eL.z + erd.z; v = fmaxf(v, 0.2f * v); ex.z = __expf(v); sm2 += ex.z;
        v = eL.w + erd.w; v = fmaxf(v, 0.2f * v); ex.w = __expf(v); sm3 += ex.w;
        *reinterpret_cast<float4*>(g_alpha + (size_t)i * 4) = ex;
    }
    #pragma unroll
    for (int off = 16; off; off >>= 1) {
        sm0 += __shfl_xor_sync(0xffffffffu, sm0, off);
        sm1 += __shfl_xor_sync(0xffffffffu, sm1, off);
        sm2 += __shfl_xor_sync(0xffffffffu, sm2, off);
        sm3 += __shfl_xor_sync(0xffffffffu, sm3, off);
    }
    int h = lane >> 3;
    float smh = (h == 0) ? sm0 : (h == 1) ? sm1 : (h == 2) ? sm2 : sm3;
    float ivh = 1.0f / fmaxf(smh, 1e-9f);
    __syncwarp();

    const unsigned int* fp = reinterpret_cast<const unsigned int*>(g_feat2h);  // 96 uints/row
    int lb = lane * 3;
    float acc[6] = {0.f, 0.f, 0.f, 0.f, 0.f, 0.f};
    for (int i = s0; i < e0; i++) {
        int sn = g_csr_src[i];
        float a = g_alpha[(size_t)i * 4 + h];
        const unsigned int* f = fp + (size_t)sn * 96 + lb;
        unsigned int u0 = f[0], u1 = f[1], u2 = f[2];
        float2 p0 = __half22float2(*reinterpret_cast<__half2*>(&u0));
        float2 p1 = __half22float2(*reinterpret_cast<__half2*>(&u1));
        float2 p2 = __half22float2(*reinterpret_cast<__half2*>(&u2));
        acc[0] = fmaf(p0.x, a, acc[0]); acc[1] = fmaf(p0.y, a, acc[1]);
        acc[2] = fmaf(p1.x, a, acc[2]); acc[3] = fmaf(p1.y, a, acc[3]);
        acc[4] = fmaf(p2.x, a, acc[4]); acc[5] = fmaf(p2.y, a, acc[5]);
    }
    int db = lane * 6;
    #pragma unroll
    for (int q = 0; q < 6; q++)
        sbuf[wl][db + q] = fmaf(acc[q], ivh, g_b2p[db + q]);
    __syncwarp();
    for (int c = lane; c < 47; c += 32) {
        float v = sbuf[wl][c] + sbuf[wl][48 + c] + sbuf[wl][96 + c] + sbuf[wl][144 + c];
        out[(size_t)w * 47 + c] = 0.25f * v;
    }
}

// ---------------- host launcher ----------------
extern "C" void kernel_launch(void* const* d_in, const int* in_sizes, int n_in,
                              void* d_out, int out_size)
{
    const float* x   = (const float*)d_in[0];
    const int*   src = (const int*)  d_in[1];
    const int*   dst = (const int*)  d_in[2];
    const int*   inv = (const int*)  d_in[3];
    const float* W1  = (const float*)d_in[4];
    const float* al1 = (const float*)d_in[5];
    const float* ar1 = (const float*)d_in[6];
    const float* b1  = (const float*)d_in[7];
    const float* W2  = (const float*)d_in[8];
    const float* al2 = (const float*)d_in[9];
    const float* ar2 = (const float*)d_in[10];
    const float* b2  = (const float*)d_in[11];
    float* out = (float*)d_out;
    (void)in_sizes; (void)n_in; (void)out_size;

    void *p_feat1 = nullptr, *p_out1 = nullptr, *p_feat2 = nullptr;
    void *p_W2p = nullptr, *p_al2p = nullptr, *p_ar2p = nullptr;
    cudaGetSymbolAddress(&p_feat1, g_feat1h);
    cudaGetSymbolAddress(&p_out1,  g_out1h);
    cudaGetSymbolAddress(&p_feat2, g_feat2h);
    cudaGetSymbolAddress(&p_W2p,   g_W2p);
    cudaGetSymbolAddress(&p_al2p,  g_al2p);
    cudaGetSymbolAddress(&p_ar2p,  g_ar2p);

    const int NP1 = N_NODES + 1;
    const int SCAN_BLOCKS = (NP1 + 1023) / 1024;
    const int EB = (N_EDGES + 255) / 256;
    const int NODE_WARP_BLOCKS = (N_NODES + 7) / 8;

    size_t gsm = (size_t)(128 * LDA + 128 * LDB) * sizeof(__half);
    cudaFuncSetAttribute((const void*)gemm_tc_k<false, false>, cudaFuncAttributeMaxDynamicSharedMemorySize, (int)gsm);
    cudaFuncSetAttribute((const void*)gemm_tc_k<true, true>,   cudaFuncAttributeMaxDynamicSharedMemorySize, (int)gsm);

    // CSR build
    zero_counts_k<<<(NP1 + 255) / 256, 256>>>(NP1);
    hist_k<<<EB, 256>>>(dst);
    scan_block_k<<<SCAN_BLOCKS, 1024>>>(NP1);
    scan_sums_k<<<1, 128>>>(SCAN_BLOCKS);
    scan_add_k<<<SCAN_BLOCKS, 1024>>>(NP1);

    // GEMM1 (independent of CSR)
    dim3 g1((N_NODES + 127) / 128, HD1 / 64);
    gemm_tc_k<false, false><<<g1, 256, gsm>>>(x, W1, (__half*)p_feat1, nullptr, N_NODES, HD1);

    // finish CSR
    zero_counts_k<<<(NP1 + 255) / 256, 256>>>(NP1);
    scatter_k<<<EB, 256>>>(src, dst);

    // ---- Layer 1 ----
    eler_k<<<NODE_WARP_BLOCKS, 256>>>((const __half*)p_feat1, al1, ar1, HD1, 32, 4);
    attn_agg1_k<<<NODE_WARP_BLOCKS, 256>>>(b1);

    // ---- Layer 2 ----
    pad2_k<<<(KIN * HD2P + 255) / 256, 256>>>(W2, b2, al2, ar2);
    dim3 g2((N_NODES + 127) / 128, HD2P / 64);
    gemm_tc_k<true, true><<<g2, 256, gsm>>>(p_out1, (const float*)p_W2p,
                                            (__half*)p_feat2, inv, N_NODES, HD2P);
    eler_k<<<NODE_WARP_BLOCKS, 256>>>((const __half*)p_feat2,
                                      (const float*)p_al2p, (const float*)p_ar2p, HD2P, 48, 6);
    attn_agg2_k<<<NODE_WARP_BLOCKS, 256>>>(out);
}

// round 6
// speedup vs baseline: 2.6754x; 1.0133x over previous
#include <cuda_runtime.h>
#include <cuda_fp16.h>
#include <math.h>
#include <stdint.h>

#define N_NODES 100000
#define N_EDGES 1600000
#define KIN 128
#define HD1 128
#define HD2P 192   // padded 4*48 (real 4*47=188)

// ---------------- scratch (static device globals; no allocation) ----------------
__device__ int    g_counts[N_NODES + 1];
__device__ int    g_rowoff[N_NODES + 1];
__device__ int    g_bsums[128];
__device__ int    g_csr_src[N_EDGES];
__device__ __half g_feat1h[(size_t)N_NODES * HD1];
__device__ __half g_out1h [(size_t)N_NODES * HD1];
__device__ __half g_feat2h[(size_t)N_NODES * HD2P];
__device__ float  g_el[N_NODES * 4];
__device__ float  g_er[N_NODES * 4];
__device__ float  g_W2p[KIN * HD2P];
__device__ float  g_b2p[HD2P];
__device__ float  g_al2p[HD2P];
__device__ float  g_ar2p[HD2P];

// ---------------- CSR build ----------------
__global__ void zero_counts_k(int n) {
    int i = blockIdx.x * blockDim.x + threadIdx.x;
    if (i < n) g_counts[i] = 0;
}
__global__ void hist_k(const int* __restrict__ dst) {
    int e = blockIdx.x * blockDim.x + threadIdx.x;
    if (e < N_EDGES) atomicAdd(&g_counts[dst[e]], 1);
}
__global__ void scan_block_k(int n) {
    __shared__ int sh[1024];
    int i = blockIdx.x * 1024 + threadIdx.x;
    int v = (i < n) ? g_counts[i] : 0;
    sh[threadIdx.x] = v;
    __syncthreads();
    for (int off = 1; off < 1024; off <<= 1) {
        int t = (threadIdx.x >= off) ? sh[threadIdx.x - off] : 0;
        __syncthreads();
        sh[threadIdx.x] += t;
        __syncthreads();
    }
    if (i < n) g_rowoff[i] = sh[threadIdx.x] - v;  // exclusive
    if (threadIdx.x == 1023) g_bsums[blockIdx.x] = sh[1023];
}
__global__ void scan_sums_k(int nb) {
    __shared__ int sh[128];
    int t = threadIdx.x;
    int v = (t < nb) ? g_bsums[t] : 0;
    sh[t] = v;
    __syncthreads();
    for (int off = 1; off < 128; off <<= 1) {
        int u = (t >= off) ? sh[t - off] : 0;
        __syncthreads();
        sh[t] += u;
        __syncthreads();
    }
    if (t < nb) g_bsums[t] = sh[t] - v;  // exclusive
}
// adds block sums AND seeds g_counts with the final row offsets (scatter cursor)
__global__ void scan_add_k(int n) {
    int i = blockIdx.x * 1024 + threadIdx.x;
    if (i < n) {
        int v = g_rowoff[i] + g_bsums[blockIdx.x];
        g_rowoff[i] = v;
        g_counts[i] = v;
    }
}
__global__ void scatter_k(const int* __restrict__ src, const int* __restrict__ dst) {
    int e = blockIdx.x * blockDim.x + threadIdx.x;
    if (e >= N_EDGES) return;
    int slot = atomicAdd(&g_counts[dst[e]], 1);
    g_csr_src[slot] = src[e];
}

// ---------------- pad layer-2 params into 4x48 layout ----------------
__global__ void pad2_k(const float* __restrict__ W2, const float* __restrict__ b2,
                       const float* __restrict__ al2, const float* __restrict__ ar2) {
    int i = blockIdx.x * blockDim.x + threadIdx.x;
    if (i < KIN * HD2P) {
        int k = i / HD2P, c = i % HD2P;
        int h = c / 48, dd = c % 48;
        g_W2p[i] = (dd < 47) ? W2[k * 188 + h * 47 + dd] : 0.0f;
    }
    if (i < HD2P) {
        int h = i / 48, dd = i % 48;
        g_b2p[i]  = (dd < 47) ? b2 [h * 47 + dd] : 0.0f;
        g_al2p[i] = (dd < 47) ? al2[h * 47 + dd] : 0.0f;
        g_ar2p[i] = (dd < 47) ? ar2[h * 47 + dd] : 0.0f;
    }
}

// ---------------- tensor-core GEMM (mma.sync m16n8k16 f16->f32) ----------------
#define LDA 136
#define LDB 72

__device__ __forceinline__ void ldsm_x4(uint32_t* r, uint32_t addr) {
    asm volatile("ldmatrix.sync.aligned.m8n8.x4.shared.b16 {%0,%1,%2,%3}, [%4];"
                 : "=r"(r[0]), "=r"(r[1]), "=r"(r[2]), "=r"(r[3]) : "r"(addr));
}
__device__ __forceinline__ void ldsm_x4t(uint32_t* r, uint32_t addr) {
    asm volatile("ldmatrix.sync.aligned.m8n8.x4.trans.shared.b16 {%0,%1,%2,%3}, [%4];"
                 : "=r"(r[0]), "=r"(r[1]), "=r"(r[2]), "=r"(r[3]) : "r"(addr));
}
__device__ __forceinline__ void mma16816(float* d, const uint32_t* a, uint32_t b0, uint32_t b1) {
    asm volatile("mma.sync.aligned.m16n8k16.row.col.f32.f16.f16.f32 "
                 "{%0,%1,%2,%3}, {%4,%5,%6,%7}, {%8,%9}, {%0,%1,%2,%3};"
                 : "+f"(d[0]), "+f"(d[1]), "+f"(d[2]), "+f"(d[3])
                 : "r"(a[0]), "r"(a[1]), "r"(a[2]), "r"(a[3]), "r"(b0), "r"(b1));
}

template <bool AHALF, bool IND>
__global__ void __launch_bounds__(256) gemm_tc_k(
    const void* __restrict__ Av, const float* __restrict__ W,
    __half* __restrict__ C, const int* __restrict__ ridx,
    int nrows, int kout)
{
    extern __shared__ __half smh[];
    __half* As = smh;                 // [128][LDA]
    __half* Bs = smh + 128 * LDA;     // [128][LDB]

    int t = threadIdx.x;
    int lane = t & 31;
    int w = t >> 5;
    int wm = w & 3;
    int wn = w >> 2;
    int rowb = blockIdx.x * 128;
    int colb = blockIdx.y * 64;

    if (AHALF) {
        const __half* A = (const __half*)Av;
        #pragma unroll
        for (int i = 0; i < 8; i++) {
            int flat = t + i * 256;
            int rl = flat >> 4;
            int c8 = (flat & 15) << 3;
            int rg = rowb + rl;
            uint4 v = make_uint4(0u, 0u, 0u, 0u);
            if (rg < nrows) {
                int ra = IND ? ridx[rg] : rg;
                v = *reinterpret_cast<const uint4*>(A + (size_t)ra * KIN + c8);
            }
            *reinterpret_cast<uint4*>(As + rl * LDA + c8) = v;
        }
    } else {
        const float* A = (const float*)Av;
        #pragma unroll
        for (int i = 0; i < 16; i++) {
            int flat = t + i * 256;
            int rl = flat >> 5;
            int k4 = (flat & 31) << 2;
            int rg = rowb + rl;
            float4 v = make_float4(0.f, 0.f, 0.f, 0.f);
            if (rg < nrows) {
                int ra = IND ? ridx[rg] : rg;
                v = *reinterpret_cast<const float4*>(A + (size_t)ra * KIN + k4);
            }
            __half2 h01 = __floats2half2_rn(v.x, v.y);
            __half2 h23 = __floats2half2_rn(v.z, v.w);
            uint2 pk = make_uint2(*reinterpret_cast<unsigned int*>(&h01),
                                  *reinterpret_cast<unsigned int*>(&h23));
            *reinterpret_cast<uint2*>(As + rl * LDA + k4) = pk;
        }
    }
    #pragma unroll
    for (int i = 0; i < 8; i++) {
        int flat = t + i * 256;
        int k  = flat >> 4;
        int c4 = (flat & 15) << 2;
        float4 v = *reinterpret_cast<const float4*>(W + (size_t)k * kout + colb + c4);
        __half2 h01 = __floats2half2_rn(v.x, v.y);
        __half2 h23 = __floats2half2_rn(v.z, v.w);
        uint2 pk = make_uint2(*reinterpret_cast<unsigned int*>(&h01),
                              *reinterpret_cast<unsigned int*>(&h23));
        *reinterpret_cast<uint2*>(Bs + k * LDB + c4) = pk;
    }
    __syncthreads();

    uint32_t sA = (uint32_t)__cvta_generic_to_shared(As);
    uint32_t sB = (uint32_t)__cvta_generic_to_shared(Bs);
    uint32_t aBase = sA + 2u * ((wm * 32 + (lane & 15)) * LDA + (lane >> 4) * 8);
    uint32_t bBase = sB + 2u * ((lane & 15) * LDB + wn * 32 + (lane >> 4) * 8);

    float d[2][4][4];
    #pragma unroll
    for (int mt = 0; mt < 2; mt++)
        #pragma unroll
        for (int nt = 0; nt < 4; nt++)
            #pragma unroll
            for (int q = 0; q < 4; q++) d[mt][nt][q] = 0.f;

    #pragma unroll
    for (int ks = 0; ks < 8; ks++) {
        uint32_t a0[4], a1[4], b0[4], b1[4];
        ldsm_x4 (a0, aBase + 2u * (ks * 16));
        ldsm_x4 (a1, aBase + 2u * (16 * LDA + ks * 16));
        ldsm_x4t(b0, bBase + 2u * (ks * 16 * LDB));
        ldsm_x4t(b1, bBase + 2u * (ks * 16 * LDB + 16));
        mma16816(d[0][0], a0, b0[0], b0[1]);
        mma16816(d[0][1], a0, b0[2], b0[3]);
        mma16816(d[0][2], a0, b1[0], b1[1]);
        mma16816(d[0][3], a0, b1[2], b1[3]);
        mma16816(d[1][0], a1, b0[0], b0[1]);
        mma16816(d[1][1], a1, b0[2], b0[3]);
        mma16816(d[1][2], a1, b1[0], b1[1]);
        mma16816(d[1][3], a1, b1[2], b1[3]);
    }

    int rbase = rowb + wm * 32 + (lane >> 2);
    int cbase = colb + wn * 32 + ((lane & 3) << 1);
    #pragma unroll
    for (int mt = 0; mt < 2; mt++) {
        int r0 = rbase + mt * 16;
        #pragma unroll
        for (int nt = 0; nt < 4; nt++) {
            int c0 = cbase + nt * 8;
            if (r0 < nrows) {
                __half2 h = __floats2half2_rn(d[mt][nt][0], d[mt][nt][1]);
                *reinterpret_cast<__half2*>(C + (size_t)r0 * kout + c0) = h;
            }
            if (r0 + 8 < nrows) {
                __half2 h = __floats2half2_rn(d[mt][nt][2], d[mt][nt][3]);
                *reinterpret_cast<__half2*>(C + (size_t)(r0 + 8) * kout + c0) = h;
            }
        }
    }
}

// ---------------- el/er: per-node per-head attention dots (half feats) ----------------
__global__ void eler_k(const __half* __restrict__ feat,
                       const float* __restrict__ al, const float* __restrict__ ar,
                       int hd, int dpad, int dpl)
{
    int w = (blockIdx.x * blockDim.x + threadIdx.x) >> 5;
    int lane = threadIdx.x & 31;
    if (w >= N_NODES) return;
    int h = lane >> 3;
    const __half* f = feat + (size_t)w * hd + lane * dpl;
    const float* alh = al + h * dpad + (lane & 7) * dpl;
    const float* arh = ar + h * dpad + (lane & 7) * dpl;
    float accL = 0.f, accR = 0.f;
    for (int q = 0; q < dpl; q++) {
        float v = __half2float(f[q]);
        accL = fmaf(v, alh[q], accL);
        accR = fmaf(v, arh[q], accR);
    }
    #pragma unroll
    for (int off = 4; off; off >>= 1) {
        accL += __shfl_xor_sync(0xffffffffu, accL, off);
        accR += __shfl_xor_sync(0xffffffffu, accR, off);
    }
    float l0 = __shfl_sync(0xffffffffu, accL, 0);
    float l1 = __shfl_sync(0xffffffffu, accL, 8);
    float l2 = __shfl_sync(0xffffffffu, accL, 16);
    float l3 = __shfl_sync(0xffffffffu, accL, 24);
    float r0 = __shfl_sync(0xffffffffu, accR, 0);
    float r1 = __shfl_sync(0xffffffffu, accR, 8);
    float r2 = __shfl_sync(0xffffffffu, accR, 16);
    float r3 = __shfl_sync(0xffffffffu, accR, 24);
    if (lane == 0) {
        *reinterpret_cast<float4*>(g_el + (size_t)w * 4) = make_float4(l0, l1, l2, l3);
        *reinterpret_cast<float4*>(g_er + (size_t)w * 4) = make_float4(r0, r1, r2, r3);
    }
}

// ---------------- SINGLE-PASS fused attention + aggregation, layer 1 ----------------
// Per edge: ex = exp(leaky(el[sn][h] + er[w][h])) computed in-lane (broadcast loads),
// accumulate Σ ex·feat and Σ ex simultaneously; normalize once at the end.
__global__ void attn_agg1_k(const float* __restrict__ b1)
{
    int w = (blockIdx.x * blockDim.x + threadIdx.x) >> 5;
    int lane = threadIdx.x & 31;
    if (w >= N_NODES) return;
    int s0 = g_rowoff[w], e0 = g_rowoff[w + 1];
    int hd = lane >> 3;
    float er_h = g_er[(size_t)w * 4 + hd];
    const uint2* fv = reinterpret_cast<const uint2*>(g_feat1h);

    float4 acc = make_float4(0.f, 0.f, 0.f, 0.f);
    float sm = 0.f;
    int i = s0;
    for (; i + 1 < e0; i += 2) {
        int s1 = g_csr_src[i];
        int s2 = g_csr_src[i + 1];
        float e1 = g_el[(size_t)s1 * 4 + hd] + er_h;
        float e2 = g_el[(size_t)s2 * 4 + hd] + er_h;
        e1 = fmaxf(e1, 0.2f * e1);
        e2 = fmaxf(e2, 0.2f * e2);
        float a1 = __expf(e1);
        float a2 = __expf(e2);
        sm += a1 + a2;
        uint2 u1 = fv[(size_t)s1 * 32 + lane];
        uint2 u2 = fv[(size_t)s2 * 32 + lane];
        float2 f10 = __half22float2(*reinterpret_cast<__half2*>(&u1.x));
        float2 f11 = __half22float2(*reinterpret_cast<__half2*>(&u1.y));
        float2 f20 = __half22float2(*reinterpret_cast<__half2*>(&u2.x));
        float2 f21 = __half22float2(*reinterpret_cast<__half2*>(&u2.y));
        acc.x = fmaf(f10.x, a1, acc.x); acc.y = fmaf(f10.y, a1, acc.y);
        acc.z = fmaf(f11.x, a1, acc.z); acc.w = fmaf(f11.y, a1, acc.w);
        acc.x = fmaf(f20.x, a2, acc.x); acc.y = fmaf(f20.y, a2, acc.y);
        acc.z = fmaf(f21.x, a2, acc.z); acc.w = fmaf(f21.y, a2, acc.w);
    }
    if (i < e0) {
        int s1 = g_csr_src[i];
        float e1 = g_el[(size_t)s1 * 4 + hd] + er_h;
        e1 = fmaxf(e1, 0.2f * e1);
        float a1 = __expf(e1);
        sm += a1;
        uint2 u1 = fv[(size_t)s1 * 32 + lane];
        float2 f10 = __half22float2(*reinterpret_cast<__half2*>(&u1.x));
        float2 f11 = __half22float2(*reinterpret_cast<__half2*>(&u1.y));
        acc.x = fmaf(f10.x, a1, acc.x); acc.y = fmaf(f10.y, a1, acc.y);
        acc.z = fmaf(f11.x, a1, acc.z); acc.w = fmaf(f11.y, a1, acc.w);
    }
    float ivh = 1.0f / fmaxf(sm, 1e-9f);
    float4 bb = *reinterpret_cast<const float4*>(b1 + lane * 4);
    acc.x = fmaf(acc.x, ivh, bb.x);
    acc.y = fmaf(acc.y, ivh, bb.y);
    acc.z = fmaf(acc.z, ivh, bb.z);
    acc.w = fmaf(acc.w, ivh, bb.w);
    acc.x = (acc.x > 0.f) ? acc.x : (__expf(acc.x) - 1.f);
    acc.y = (acc.y > 0.f) ? acc.y : (__expf(acc.y) - 1.f);
    acc.z = (acc.z > 0.f) ? acc.z : (__expf(acc.z) - 1.f);
    acc.w = (acc.w > 0.f) ? acc.w : (__expf(acc.w) - 1.f);
    __half2 h01 = __floats2half2_rn(acc.x, acc.y);
    __half2 h23 = __floats2half2_rn(acc.z, acc.w);
    uint2 pk = make_uint2(*reinterpret_cast<unsigned int*>(&h01),
                          *reinterpret_cast<unsigned int*>(&h23));
    *reinterpret_cast<uint2*>(g_out1h + (size_t)w * HD1 + lane * 4) = pk;
}

// ---------------- SINGLE-PASS fused attention + aggregation, layer 2 ----------------
__global__ void attn_agg2_k(float* __restrict__ out)
{
    __shared__ float sbuf[8][HD2P];
    int wl = threadIdx.x >> 5;
    int w = blockIdx.x * 8 + wl;
    int lane = threadIdx.x & 31;
    if (w >= N_NODES) return;
    int s0 = g_rowoff[w], e0 = g_rowoff[w + 1];
    int h = lane >> 3;
    float er_h = g_er[(size_t)w * 4 + h];
    const unsigned int* fp = reinterpret_cast<const unsigned int*>(g_feat2h);  // 96 uints/row
    int lb = lane * 3;

    float acc[6] = {0.f, 0.f, 0.f, 0.f, 0.f, 0.f};
    float sm = 0.f;
    for (int i = s0; i < e0; i++) {
        int sn = g_csr_src[i];
        float e = g_el[(size_t)sn * 4 + h] + er_h;
        e = fmaxf(e, 0.2f * e);
        float a = __expf(e);
        sm += a;
        const unsigned int* f = fp + (size_t)sn * 96 + lb;
        unsigned int u0 = f[0], u1 = f[1], u2 = f[2];
        float2 p0 = __half22float2(*reinterpret_cast<__half2*>(&u0));
        float2 p1 = __half22float2(*reinterpret_cast<__half2*>(&u1));
        float2 p2 = __half22float2(*reinterpret_cast<__half2*>(&u2));
        acc[0] = fmaf(p0.x, a, acc[0]); acc[1] = fmaf(p0.y, a, acc[1]);
        acc[2] = fmaf(p1.x, a, acc[2]); acc[3] = fmaf(p1.y, a, acc[3]);
        acc[4] = fmaf(p2.x, a, acc[4]); acc[5] = fmaf(p2.y, a, acc[5]);
    }
    float ivh = 1.0f / fmaxf(sm, 1e-9f);
    int db = lane * 6;
    #pragma unroll
    for (int q = 0; q < 6; q++)
        sbuf[wl][db + q] = fmaf(acc[q], ivh, g_b2p[db + q]);
    __syncwarp();
    for (int c = lane; c < 47; c += 32) {
        float v = sbuf[wl][c] + sbuf[wl][48 + c] + sbuf[wl][96 + c] + sbuf[wl][144 + c];
        out[(size_t)w * 47 + c] = 0.25f * v;
    }
}

// ---------------- host launcher ----------------
extern "C" void kernel_launch(void* const* d_in, const int* in_sizes, int n_in,
                              void* d_out, int out_size)
{
    const float* x   = (const float*)d_in[0];
    const int*   src = (const int*)  d_in[1];
    const int*   dst = (const int*)  d_in[2];
    const int*   inv = (const int*)  d_in[3];
    const float* W1  = (const float*)d_in[4];
    const float* al1 = (const float*)d_in[5];
    const float* ar1 = (const float*)d_in[6];
    const float* b1  = (const float*)d_in[7];
    const float* W2  = (const float*)d_in[8];
    const float* al2 = (const float*)d_in[9];
    const float* ar2 = (const float*)d_in[10];
    const float* b2  = (const float*)d_in[11];
    float* out = (float*)d_out;
    (void)in_sizes; (void)n_in; (void)out_size;

    void *p_feat1 = nullptr, *p_out1 = nullptr, *p_feat2 = nullptr;
    void *p_W2p = nullptr, *p_al2p = nullptr, *p_ar2p = nullptr;
    cudaGetSymbolAddress(&p_feat1, g_feat1h);
    cudaGetSymbolAddress(&p_out1,  g_out1h);
    cudaGetSymbolAddress(&p_feat2, g_feat2h);
    cudaGetSymbolAddress(&p_W2p,   g_W2p);
    cudaGetSymbolAddress(&p_al2p,  g_al2p);
    cudaGetSymbolAddress(&p_ar2p,  g_ar2p);

    const int NP1 = N_NODES + 1;
    const int SCAN_BLOCKS = (NP1 + 1023) / 1024;
    const int EB = (N_EDGES + 255) / 256;
    const int NODE_WARP_BLOCKS = (N_NODES + 7) / 8;

    size_t gsm = (size_t)(128 * LDA + 128 * LDB) * sizeof(__half);
    cudaFuncSetAttribute((const void*)gemm_tc_k<false, false>, cudaFuncAttributeMaxDynamicSharedMemorySize, (int)gsm);
    cudaFuncSetAttribute((const void*)gemm_tc_k<true, true>,   cudaFuncAttributeMaxDynamicSharedMemorySize, (int)gsm);

    // CSR build (scan_add seeds the scatter cursor; no second zero pass)
    zero_counts_k<<<(NP1 + 255) / 256, 256>>>(NP1);
    hist_k<<<EB, 256>>>(dst);
    scan_block_k<<<SCAN_BLOCKS, 1024>>>(NP1);
    scan_sums_k<<<1, 128>>>(SCAN_BLOCKS);
    scan_add_k<<<SCAN_BLOCKS, 1024>>>(NP1);

    // GEMM1 (independent of CSR)
    dim3 g1((N_NODES + 127) / 128, HD1 / 64);
    gemm_tc_k<false, false><<<g1, 256, gsm>>>(x, W1, (__half*)p_feat1, nullptr, N_NODES, HD1);

    scatter_k<<<EB, 256>>>(src, dst);

    // ---- Layer 1 ----
    eler_k<<<NODE_WARP_BLOCKS, 256>>>((const __half*)p_feat1, al1, ar1, HD1, 32, 4);
    attn_agg1_k<<<NODE_WARP_BLOCKS, 256>>>(b1);

    // ---- Layer 2 ----
    pad2_k<<<(KIN * HD2P + 255) / 256, 256>>>(W2, b2, al2, ar2);
    dim3 g2((N_NODES + 127) / 128, HD2P / 64);
    gemm_tc_k<true, true><<<g2, 256, gsm>>>(p_out1, (const float*)p_W2p,
                                            (__half*)p_feat2, inv, N_NODES, HD2P);
    eler_k<<<NODE_WARP_BLOCKS, 256>>>((const __half*)p_feat2,
                                      (const float*)p_al2p, (const float*)p_ar2p, HD2P, 48, 6);
    attn_agg2_k<<<NODE_WARP_BLOCKS, 256>>>(out);
}